// round 5
// baseline (speedup 1.0000x reference)
#include <cuda_runtime.h>

typedef unsigned long long ull;

// ---------------- problem constants (shapes fixed by the dataset) -----------
#define MAXN 100000
#define MAXE 3342336
#define HC   64
#define EPSV 1e-5f

// ---------------- device scratch (static; no allocation) --------------------
__device__ float g_bufA[MAXN * HC];      // projected features (xW)
__device__ float g_bufB[MAXN * HC];      // aggregated features (h)
__device__ float g_dis[MAXN];            // rsqrt(deg)
__device__ int   g_deg[MAXN];            // in-degree (w/o self loop)
__device__ int   g_rowptr[MAXN + 1];
__device__ int   g_cursor[MAXN];
__device__ int   g_csr[MAXE];            // src ids grouped by dst
__device__ int   g_bsum[512];
__device__ int   g_boff[512];
__device__ float g_sum1[HC], g_sq1[HC], g_sum2[HC], g_sq2[HC];
__device__ int   g_is64;

// ---------------- dtype-agnostic index load ---------------------------------
__device__ __forceinline__ long long ld_idx(const void* p, long long i) {
    if (g_is64) return ((const long long*)p)[i];
    return (long long)((const int*)p)[i];
}

__global__ void k_detect(const void* ei, long long n_nodes) {
    const long long* p = (const long long*)ei;
    int ok = 1;
    for (int i = 0; i < 64; i++) {
        long long v = p[i];
        if (v < 0 || v >= n_nodes) { ok = 0; break; }
    }
    g_is64 = ok;
}

// ---------------- packed f32x2 helpers (Blackwell) --------------------------
__device__ __forceinline__ ull dupf(float a) {
    ull r; unsigned int u = __float_as_uint(a);
    asm("mov.b64 %0, {%1, %1};" : "=l"(r) : "r"(u));
    return r;
}
__device__ __forceinline__ void ffma2(ull& d, ull a, ull b) {
    asm("fma.rn.f32x2 %0, %1, %2, %0;" : "+l"(d) : "l"(a), "l"(b));
}
__device__ __forceinline__ float2 unpk(ull v) {
    unsigned int lo, hi;
    asm("mov.b64 {%0, %1}, %2;" : "=r"(lo), "=r"(hi) : "l"(v));
    return make_float2(__uint_as_float(lo), __uint_as_float(hi));
}

// ---------------- init ---------------------------------------------------------
__global__ void k_zero(long long n) {
    long long i = blockIdx.x * (long long)blockDim.x + threadIdx.x;
    if (i < n) g_deg[i] = 0;
    if (i < HC) { g_sum1[i] = 0.f; g_sq1[i] = 0.f; g_sum2[i] = 0.f; g_sq2[i] = 0.f; }
}

__global__ void k_hist(const void* ei, long long E) {
    long long e = blockIdx.x * (long long)blockDim.x + threadIdx.x;
    if (e >= E) return;
    atomicAdd(&g_deg[ld_idx(ei, E + e)], 1);
}

// ---------------- exclusive scan over g_deg ------------------------------------
__global__ void k_scan1(long long n) {
    __shared__ int wsum[8];
    int t = threadIdx.x;
    long long i = blockIdx.x * 256LL + t;
    int v = (i < n) ? g_deg[i] : 0;
    int x = v;
#pragma unroll
    for (int o = 1; o < 32; o <<= 1) {
        int y = __shfl_up_sync(~0u, x, o);
        if ((t & 31) >= o) x += y;
    }
    if ((t & 31) == 31) wsum[t >> 5] = x;
    __syncthreads();
    if (t < 8) {
        int y = wsum[t];
#pragma unroll
        for (int o = 1; o < 8; o <<= 1) {
            int z = __shfl_up_sync(0xff, y, o);
            if (t >= o) y += z;
        }
        wsum[t] = y;
    }
    __syncthreads();
    int base = (t >= 32) ? wsum[(t >> 5) - 1] : 0;
    int incl = x + base;
    if (i < n) g_rowptr[i] = incl - v;
    if (t == 255) g_bsum[blockIdx.x] = incl;
}

__global__ void k_scan2(int nb) {
    __shared__ int wsum[16];
    int t = threadIdx.x;
    int v = (t < nb) ? g_bsum[t] : 0;
    int x = v;
#pragma unroll
    for (int o = 1; o < 32; o <<= 1) {
        int y = __shfl_up_sync(~0u, x, o);
        if ((t & 31) >= o) x += y;
    }
    if ((t & 31) == 31) wsum[t >> 5] = x;
    __syncthreads();
    if (t < 16) {
        int y = wsum[t];
#pragma unroll
        for (int o = 1; o < 16; o <<= 1) {
            int z = __shfl_up_sync(0xffff, y, o);
            if (t >= o) y += z;
        }
        wsum[t] = y;
    }
    __syncthreads();
    int base = (t >= 32) ? wsum[(t >> 5) - 1] : 0;
    g_boff[t] = x + base - v;
}

__global__ void k_scan3(long long n, int E) {
    long long i = blockIdx.x * (long long)blockDim.x + threadIdx.x;
    if (i < n) {
        int rp = g_rowptr[i] + g_boff[i >> 8];
        g_rowptr[i] = rp;
        g_cursor[i] = rp;
        g_dis[i] = rsqrtf((float)(g_deg[i] + 1));
    }
    if (i == 0) g_rowptr[n] = E;
}

__global__ void k_scatter(const void* ei, long long E) {
    long long e = blockIdx.x * (long long)blockDim.x + threadIdx.x;
    if (e >= E) return;
    long long s = ld_idx(ei, e);
    long long d = ld_idx(ei, E + e);
    int pos = atomicAdd(&g_cursor[d], 1);
    g_csr[pos] = (int)s;
}

// ---------------- GEMM: C[N,64] = bn?(A)[N,K] @ W[K,64] ----------------------
// 64 threads, block tile 64x64, thread tile 8x8, packed f32x2 accumulators.
template <int K, bool BN>
__global__ void k_gemm(const float* __restrict__ A, const float* __restrict__ W,
                       float* __restrict__ C, long long n,
                       const float* __restrict__ gsum, const float* __restrict__ gsq,
                       const float* __restrict__ gamma, const float* __restrict__ beta,
                       float invN) {
    __shared__ __align__(16) float xsT[16][64];   // [k][row] — STS conflict-free
    __shared__ __align__(16) float ws[16][64];    // [k][col]
    __shared__ float bnsc[64], bnsh[64];
    const int tid = threadIdx.x;
    const int tx = tid & 7;        // col group (8 cols)
    const int ty = tid >> 3;       // row group (8 rows)
    const long long row0 = (long long)blockIdx.x * 64;
    ull acc[8][4] = {};

    if (BN && tid < 64) {
        float m   = gsum[tid] * invN;
        float var = gsq[tid] * invN - m * m;
        float s   = rsqrtf(var + EPSV) * gamma[tid];
        bnsc[tid] = s;
        bnsh[tid] = beta[tid] - m * s;
    }
    if (BN) __syncthreads();

    const long long myrow = row0 + tid;
    const bool rok = myrow < n;

    for (int k0 = 0; k0 < K; k0 += 16) {
        // stage: global loads into registers
        float4 xv[4];
        if (rok) {
            const float* src = A + myrow * (long long)K + k0;
#pragma unroll
            for (int q = 0; q < 4; q++) xv[q] = *(const float4*)(src + q * 4);
            if (BN) {
#pragma unroll
                for (int q = 0; q < 4; q++) {
                    int c = k0 + q * 4;
                    xv[q].x = xv[q].x * bnsc[c + 0] + bnsh[c + 0];
                    xv[q].y = xv[q].y * bnsc[c + 1] + bnsh[c + 1];
                    xv[q].z = xv[q].z * bnsc[c + 2] + bnsh[c + 2];
                    xv[q].w = xv[q].w * bnsc[c + 3] + bnsh[c + 3];
                }
            }
        } else {
#pragma unroll
            for (int q = 0; q < 4; q++) xv[q] = make_float4(0.f, 0.f, 0.f, 0.f);
        }
        float4 wv[4];
#pragma unroll
        for (int j = 0; j < 4; j++) {
            int s = tid + 64 * j;
            int kk = s >> 4;
            int cc = (s & 15) * 4;
            wv[j] = *(const float4*)(W + (long long)(k0 + kk) * 64 + cc);
        }
        __syncthreads();   // previous iteration's compute done
#pragma unroll
        for (int q = 0; q < 4; q++) {
            xsT[q * 4 + 0][tid] = xv[q].x;
            xsT[q * 4 + 1][tid] = xv[q].y;
            xsT[q * 4 + 2][tid] = xv[q].z;
            xsT[q * 4 + 3][tid] = xv[q].w;
        }
#pragma unroll
        for (int j = 0; j < 4; j++) {
            int s = tid + 64 * j;
            int kk = s >> 4;
            int cc = (s & 15) * 4;
            *(float4*)&ws[kk][cc] = wv[j];
        }
        __syncthreads();
#pragma unroll
        for (int kk = 0; kk < 16; kk++) {
            float4 a0 = *(const float4*)&xsT[kk][ty * 8];
            float4 a1 = *(const float4*)&xsT[kk][ty * 8 + 4];
            const ull* bp = (const ull*)&ws[kk][tx * 8];
            ull b0 = bp[0], b1 = bp[1], b2 = bp[2], b3 = bp[3];
            ull a;
            a = dupf(a0.x); ffma2(acc[0][0], a, b0); ffma2(acc[0][1], a, b1); ffma2(acc[0][2], a, b2); ffma2(acc[0][3], a, b3);
            a = dupf(a0.y); ffma2(acc[1][0], a, b0); ffma2(acc[1][1], a, b1); ffma2(acc[1][2], a, b2); ffma2(acc[1][3], a, b3);
            a = dupf(a0.z); ffma2(acc[2][0], a, b0); ffma2(acc[2][1], a, b1); ffma2(acc[2][2], a, b2); ffma2(acc[2][3], a, b3);
            a = dupf(a0.w); ffma2(acc[3][0], a, b0); ffma2(acc[3][1], a, b1); ffma2(acc[3][2], a, b2); ffma2(acc[3][3], a, b3);
            a = dupf(a1.x); ffma2(acc[4][0], a, b0); ffma2(acc[4][1], a, b1); ffma2(acc[4][2], a, b2); ffma2(acc[4][3], a, b3);
            a = dupf(a1.y); ffma2(acc[5][0], a, b0); ffma2(acc[5][1], a, b1); ffma2(acc[5][2], a, b2); ffma2(acc[5][3], a, b3);
            a = dupf(a1.z); ffma2(acc[6][0], a, b0); ffma2(acc[6][1], a, b1); ffma2(acc[6][2], a, b2); ffma2(acc[6][3], a, b3);
            a = dupf(a1.w); ffma2(acc[7][0], a, b0); ffma2(acc[7][1], a, b1); ffma2(acc[7][2], a, b2); ffma2(acc[7][3], a, b3);
        }
    }
#pragma unroll
    for (int i = 0; i < 8; i++) {
        long long row = row0 + ty * 8 + i;
        if (row < n) {
            float2 c0 = unpk(acc[i][0]), c1 = unpk(acc[i][1]);
            float2 c2 = unpk(acc[i][2]), c3 = unpk(acc[i][3]);
            float* dst = C + row * 64 + tx * 8;
            *(float4*)dst       = make_float4(c0.x, c0.y, c1.x, c1.y);
            *(float4*)(dst + 4) = make_float4(c2.x, c2.y, c3.x, c3.y);
        }
    }
}

// ---------------- fused CSR gather: self loop + bias + agg + relu + stats ---
__global__ void k_gather(const float* __restrict__ xw, const float* __restrict__ bias,
                         float* __restrict__ out, long long n,
                         float* __restrict__ gsum, float* __restrict__ gsq) {
    __shared__ float ss[HC], sq[HC];
    int t = threadIdx.x;
    if (t < HC) { ss[t] = 0.f; sq[t] = 0.f; }
    __syncthreads();
    int grp = t >> 4;
    int ch  = (t & 15) * 4;
    long long node = blockIdx.x * 16LL + grp;
    if (node < n) {
        float dd = g_dis[node];
        float4 bv = *(const float4*)(bias + ch);
        float4 xv = *(const float4*)(xw + node * 64 + ch);
        float w0 = dd * dd;
        float4 acc = make_float4(bv.x + w0 * xv.x, bv.y + w0 * xv.y,
                                 bv.z + w0 * xv.z, bv.w + w0 * xv.w);
        int beg = g_rowptr[node], end = g_rowptr[node + 1];
        int i = beg;
        for (; i + 4 <= end; i += 4) {
            int s0 = g_csr[i], s1 = g_csr[i + 1], s2 = g_csr[i + 2], s3 = g_csr[i + 3];
            float n0 = dd * g_dis[s0], n1 = dd * g_dis[s1];
            float n2 = dd * g_dis[s2], n3 = dd * g_dis[s3];
            float4 v0 = *(const float4*)(xw + (long long)s0 * 64 + ch);
            float4 v1 = *(const float4*)(xw + (long long)s1 * 64 + ch);
            float4 v2 = *(const float4*)(xw + (long long)s2 * 64 + ch);
            float4 v3 = *(const float4*)(xw + (long long)s3 * 64 + ch);
            acc.x += n0 * v0.x + n1 * v1.x + n2 * v2.x + n3 * v3.x;
            acc.y += n0 * v0.y + n1 * v1.y + n2 * v2.y + n3 * v3.y;
            acc.z += n0 * v0.z + n1 * v1.z + n2 * v2.z + n3 * v3.z;
            acc.w += n0 * v0.w + n1 * v1.w + n2 * v2.w + n3 * v3.w;
        }
        for (; i < end; i++) {
            int s = g_csr[i];
            float nn = dd * g_dis[s];
            float4 v = *(const float4*)(xw + (long long)s * 64 + ch);
            acc.x += nn * v.x; acc.y += nn * v.y;
            acc.z += nn * v.z; acc.w += nn * v.w;
        }
        acc.x = fmaxf(acc.x, 0.f); acc.y = fmaxf(acc.y, 0.f);
        acc.z = fmaxf(acc.z, 0.f); acc.w = fmaxf(acc.w, 0.f);
        *(float4*)(out + node * 64 + ch) = acc;
        atomicAdd(&ss[ch + 0], acc.x); atomicAdd(&sq[ch + 0], acc.x * acc.x);
        atomicAdd(&ss[ch + 1], acc.y); atomicAdd(&sq[ch + 1], acc.y * acc.y);
        atomicAdd(&ss[ch + 2], acc.z); atomicAdd(&sq[ch + 2], acc.z * acc.z);
        atomicAdd(&ss[ch + 3], acc.w); atomicAdd(&sq[ch + 3], acc.w * acc.w);
    }
    __syncthreads();
    if (t < HC) { atomicAdd(&gsum[t], ss[t]); atomicAdd(&gsq[t], sq[t]); }
}

// ---------------- fused BN2 + mean pool + MLP: one block per graph -----------
__global__ void k_poolmlp(const float* __restrict__ buf, const float* __restrict__ gsum,
                          const float* __restrict__ gsq, const float* __restrict__ gamma,
                          const float* __restrict__ beta, const void* batch,
                          float invN, long long n,
                          const float* __restrict__ fw1, const float* __restrict__ fb1,
                          const float* __restrict__ fw2, const float* __restrict__ fb2,
                          const float* __restrict__ fw3, const float* __restrict__ fb3,
                          const float* __restrict__ fw4, const float* __restrict__ fb4,
                          const float* __restrict__ ow,  const float* __restrict__ ob,
                          float* __restrict__ out) {
    __shared__ float sc[64], sh[64], p[64], part[256];
    __shared__ float a1[128], a2[64], a3[32], a4[16];
    __shared__ int seg[2];
    int g = blockIdx.x, t = threadIdx.x;
    if (t < 64) {
        float m   = gsum[t] * invN;
        float var = gsq[t] * invN - m * m;
        float s   = rsqrtf(var + EPSV) * gamma[t];
        sc[t] = s; sh[t] = beta[t] - m * s;
    }
    if (t < 2) {   // lower_bound(batch, g + t): batch is sorted
        long long target = g + t;
        long long lo = 0, hi = n;
        while (lo < hi) {
            long long mid = (lo + hi) >> 1;
            if (ld_idx(batch, mid) < target) lo = mid + 1; else hi = mid;
        }
        seg[t] = (int)lo;
    }
    __syncthreads();
    int beg = seg[0], end = seg[1];
    int c = t & 63, grp = t >> 6;
    float s = 0.f;
    for (long long node = beg + grp; node < end; node += 4)
        s += buf[node * 64 + c] * sc[c] + sh[c];
    part[t] = s;
    __syncthreads();
    if (t < 64) {
        float cnt = (float)(end - beg);
        p[t] = (part[t] + part[t + 64] + part[t + 128] + part[t + 192]) / fmaxf(cnt, 1.f);
    }
    __syncthreads();
    if (t < 128) {
        float a = fb1[t];
#pragma unroll 8
        for (int k = 0; k < 64; k++) a += p[k] * fw1[k * 128 + t];
        a1[t] = fmaxf(a, 0.f);
    }
    __syncthreads();
    if (t < 64) {
        float a = fb2[t];
#pragma unroll 8
        for (int k = 0; k < 128; k++) a += a1[k] * fw2[k * 64 + t];
        a2[t] = fmaxf(a, 0.f);
    }
    __syncthreads();
    if (t < 32) {
        float a = fb3[t];
#pragma unroll 8
        for (int k = 0; k < 64; k++) a += a2[k] * fw3[k * 32 + t];
        a3[t] = fmaxf(a, 0.f);
    }
    __syncthreads();
    if (t < 16) {
        float a = fb4[t];
#pragma unroll
        for (int k = 0; k < 32; k++) a += a3[k] * fw4[k * 16 + t];
        a4[t] = fmaxf(a, 0.f);
    }
    __syncthreads();
    if (t < 2) {
        float a = ob[t];
#pragma unroll
        for (int k = 0; k < 16; k++) a += a4[k] * ow[k * 2 + t];
        out[g * 2 + t] = a;
    }
}

// ---------------- launcher ------------------------------------------------------
extern "C" void kernel_launch(void* const* d_in, const int* in_sizes, int n_in,
                              void* d_out, int out_size) {
    const float* x   = (const float*)d_in[0];
    const void*  ei  = d_in[1];
    const void*  bat = d_in[2];
    const float* w1  = (const float*)d_in[3];
    const float* b1  = (const float*)d_in[4];
    const float* w2  = (const float*)d_in[5];
    const float* b2  = (const float*)d_in[6];
    const float* g1  = (const float*)d_in[7];
    const float* be1 = (const float*)d_in[8];
    const float* g2  = (const float*)d_in[9];
    const float* be2 = (const float*)d_in[10];
    const float* fw1 = (const float*)d_in[11];
    const float* fb1 = (const float*)d_in[12];
    const float* fw2 = (const float*)d_in[13];
    const float* fb2 = (const float*)d_in[14];
    const float* fw3 = (const float*)d_in[15];
    const float* fb3 = (const float*)d_in[16];
    const float* fw4 = (const float*)d_in[17];
    const float* fb4 = (const float*)d_in[18];
    const float* ow  = (const float*)d_in[19];
    const float* ob  = (const float*)d_in[20];
    float* out = (float*)d_out;

    const long long N = in_sizes[0] / 256;   // C = 256
    const long long E = in_sizes[1] / 2;
    const int       G = out_size / 2;
    const float invN = 1.0f / (float)N;

    float *bufA, *bufB, *sum1, *sq1, *sum2, *sq2;
    cudaGetSymbolAddress((void**)&bufA, g_bufA);
    cudaGetSymbolAddress((void**)&bufB, g_bufB);
    cudaGetSymbolAddress((void**)&sum1, g_sum1);
    cudaGetSymbolAddress((void**)&sq1,  g_sq1);
    cudaGetSymbolAddress((void**)&sum2, g_sum2);
    cudaGetSymbolAddress((void**)&sq2,  g_sq2);

    const int TB = 256;
    const int gN    = (int)((N + TB - 1) / TB);
    const int gE    = (int)((E + TB - 1) / TB);
    const int gGemm = (int)((N + 63) / 64);
    const int gGath = (int)((N + 15) / 16);
    const int nb    = (int)((N + 255) / 256);

    // ---- index dtype + CSR build ----
    k_detect<<<1, 1>>>(ei, N);
    k_zero<<<gN, TB>>>(N);
    k_hist<<<gE, TB>>>(ei, E);
    k_scan1<<<nb, 256>>>(N);
    k_scan2<<<1, 512>>>(nb);
    k_scan3<<<gN, TB>>>(N, (int)E);
    k_scatter<<<gE, TB>>>(ei, E);

    // ---- GCN layer 1 ----
    k_gemm<256, false><<<gGemm, 64>>>(x, w1, bufA, N, nullptr, nullptr, nullptr, nullptr, 0.f);
    k_gather<<<gGath, 256>>>(bufA, b1, bufB, N, sum1, sq1);

    // ---- GCN layer 2 (BN1 folded into A-load) ----
    k_gemm<64, true><<<gGemm, 64>>>(bufB, w2, bufA, N, sum1, sq1, g1, be1, invN);
    k_gather<<<gGath, 256>>>(bufA, b2, bufB, N, sum2, sq2);

    // ---- fused BN2 + pool + MLP head ----
    k_poolmlp<<<G, 256>>>(bufB, sum2, sq2, g2, be2, bat, invN, N,
                          fw1, fb1, fw2, fb2, fw3, fb3, fw4, fb4, ow, ob, out);
}

// round 6
// speedup vs baseline: 1.0230x; 1.0230x over previous
#include <cuda_runtime.h>

typedef unsigned long long ull;

// ---------------- problem constants (shapes fixed by the dataset) -----------
#define MAXN 100000
#define MAXE 3342336
#define HC   64
#define EPSV 1e-5f

// ---------------- device scratch (static; no allocation) --------------------
__device__ float g_bufA[MAXN * HC];      // projected features (xW)
__device__ float g_bufB[MAXN * HC];      // aggregated features (h)
__device__ float g_dis[MAXN];            // rsqrt(deg)
__device__ int   g_deg[MAXN];            // in-degree (w/o self loop)
__device__ int   g_rowptr[MAXN + 1];
__device__ int   g_cursor[MAXN];
__device__ int   g_csr[MAXE];            // src ids grouped by dst
__device__ int   g_bsum[512];
__device__ int   g_boff[512];
__device__ float g_sum1[HC], g_sq1[HC], g_sum2[HC], g_sq2[HC];
__device__ int   g_is64;

// ---------------- dtype-agnostic index load ---------------------------------
__device__ __forceinline__ long long ld_idx(const void* p, long long i) {
    if (g_is64) return ((const long long*)p)[i];
    return (long long)((const int*)p)[i];
}

// ---------------- packed f32x2 helpers (Blackwell) --------------------------
__device__ __forceinline__ ull dupf(float a) {
    ull r; unsigned int u = __float_as_uint(a);
    asm("mov.b64 %0, {%1, %1};" : "=l"(r) : "r"(u));
    return r;
}
__device__ __forceinline__ void ffma2(ull& d, ull a, ull b) {
    asm("fma.rn.f32x2 %0, %1, %2, %0;" : "+l"(d) : "l"(a), "l"(b));
}
__device__ __forceinline__ float2 unpk(ull v) {
    unsigned int lo, hi;
    asm("mov.b64 {%0, %1}, %2;" : "=r"(lo), "=r"(hi) : "l"(v));
    return make_float2(__uint_as_float(lo), __uint_as_float(hi));
}

// ---------------- init (+ index dtype detection in thread 0) -----------------
__global__ void k_zero(const void* ei, long long n) {
    long long i = blockIdx.x * (long long)blockDim.x + threadIdx.x;
    if (i == 0) {
        const long long* p = (const long long*)ei;
        int ok = 1;
        for (int j = 0; j < 64; j++) {
            long long v = p[j];
            if (v < 0 || v >= n) { ok = 0; break; }
        }
        g_is64 = ok;
    }
    if (i < n) g_deg[i] = 0;
    if (i < HC) { g_sum1[i] = 0.f; g_sq1[i] = 0.f; g_sum2[i] = 0.f; g_sq2[i] = 0.f; }
}

__global__ void k_hist(const void* ei, long long E) {
    long long e = blockIdx.x * (long long)blockDim.x + threadIdx.x;
    if (e >= E) return;
    atomicAdd(&g_deg[ld_idx(ei, E + e)], 1);
}

// ---------------- exclusive scan over g_deg ------------------------------------
__global__ void k_scan1(long long n) {
    __shared__ int wsum[8];
    int t = threadIdx.x;
    long long i = blockIdx.x * 256LL + t;
    int v = (i < n) ? g_deg[i] : 0;
    int x = v;
#pragma unroll
    for (int o = 1; o < 32; o <<= 1) {
        int y = __shfl_up_sync(~0u, x, o);
        if ((t & 31) >= o) x += y;
    }
    if ((t & 31) == 31) wsum[t >> 5] = x;
    __syncthreads();
    if (t < 8) {
        int y = wsum[t];
#pragma unroll
        for (int o = 1; o < 8; o <<= 1) {
            int z = __shfl_up_sync(0xff, y, o);
            if (t >= o) y += z;
        }
        wsum[t] = y;
    }
    __syncthreads();
    int base = (t >= 32) ? wsum[(t >> 5) - 1] : 0;
    int incl = x + base;
    if (i < n) g_rowptr[i] = incl - v;
    if (t == 255) g_bsum[blockIdx.x] = incl;
}

__global__ void k_scan2(int nb) {
    __shared__ int wsum[16];
    int t = threadIdx.x;
    int v = (t < nb) ? g_bsum[t] : 0;
    int x = v;
#pragma unroll
    for (int o = 1; o < 32; o <<= 1) {
        int y = __shfl_up_sync(~0u, x, o);
        if ((t & 31) >= o) x += y;
    }
    if ((t & 31) == 31) wsum[t >> 5] = x;
    __syncthreads();
    if (t < 16) {
        int y = wsum[t];
#pragma unroll
        for (int o = 1; o < 16; o <<= 1) {
            int z = __shfl_up_sync(0xffff, y, o);
            if (t >= o) y += z;
        }
        wsum[t] = y;
    }
    __syncthreads();
    int base = (t >= 32) ? wsum[(t >> 5) - 1] : 0;
    g_boff[t] = x + base - v;
}

__global__ void k_scan3(long long n, int E) {
    long long i = blockIdx.x * (long long)blockDim.x + threadIdx.x;
    if (i < n) {
        int rp = g_rowptr[i] + g_boff[i >> 8];
        g_rowptr[i] = rp;
        g_cursor[i] = rp;
        g_dis[i] = rsqrtf((float)(g_deg[i] + 1));
    }
    if (i == 0) g_rowptr[n] = E;
}

__global__ void k_scatter(const void* ei, long long E) {
    long long e = blockIdx.x * (long long)blockDim.x + threadIdx.x;
    if (e >= E) return;
    long long s = ld_idx(ei, e);
    long long d = ld_idx(ei, E + e);
    int pos = atomicAdd(&g_cursor[d], 1);
    g_csr[pos] = (int)s;
}

// ---------------- GEMM: C[N,64] = bn?(A)[N,K] @ W[K,64] ----------------------
// Round-3 proven config: 128 threads, block tile 32x64, thread tile 4x4,
// packed f32x2 accumulators. Optional BN affine fold on A-load.
template <int K, bool BN>
__global__ void k_gemm(const float* __restrict__ A, const float* __restrict__ W,
                       float* __restrict__ C, long long n,
                       const float* __restrict__ gsum, const float* __restrict__ gsq,
                       const float* __restrict__ gamma, const float* __restrict__ beta,
                       float invN) {
    __shared__ __align__(16) float xsT[32][36];
    __shared__ __align__(16) float ws[32][64];
    __shared__ float bnsc[64], bnsh[64];
    const int tid = threadIdx.x;
    const int tx = tid & 15;        // column group (4 cols = 2 pairs)
    const int ty = tid >> 4;        // row group    (4 rows)
    const long long row0 = (long long)blockIdx.x * 32;
    ull acc[4][2] = {};

    if (BN) {
        if (tid < 64) {
            float m   = gsum[tid] * invN;
            float var = gsq[tid] * invN - m * m;
            float s   = rsqrtf(var + EPSV) * gamma[tid];
            bnsc[tid] = s;
            bnsh[tid] = beta[tid] - m * s;
        }
        __syncthreads();
    }

    for (int k0 = 0; k0 < K; k0 += 32) {
        {
            int r  = tid >> 2;
            int kk = (tid & 3) * 8;
            long long row = row0 + r;
            float4 v0 = make_float4(0.f, 0.f, 0.f, 0.f), v1 = v0;
            if (row < n) {
                const float* src = A + row * (long long)K + k0 + kk;
                v0 = *(const float4*)src;
                v1 = *(const float4*)(src + 4);
                if (BN) {
                    int c = k0 + kk;
                    v0.x = v0.x * bnsc[c + 0] + bnsh[c + 0];
                    v0.y = v0.y * bnsc[c + 1] + bnsh[c + 1];
                    v0.z = v0.z * bnsc[c + 2] + bnsh[c + 2];
                    v0.w = v0.w * bnsc[c + 3] + bnsh[c + 3];
                    v1.x = v1.x * bnsc[c + 4] + bnsh[c + 4];
                    v1.y = v1.y * bnsc[c + 5] + bnsh[c + 5];
                    v1.z = v1.z * bnsc[c + 6] + bnsh[c + 6];
                    v1.w = v1.w * bnsc[c + 7] + bnsh[c + 7];
                }
            }
            xsT[kk + 0][r] = v0.x; xsT[kk + 1][r] = v0.y;
            xsT[kk + 2][r] = v0.z; xsT[kk + 3][r] = v0.w;
            xsT[kk + 4][r] = v1.x; xsT[kk + 5][r] = v1.y;
            xsT[kk + 6][r] = v1.z; xsT[kk + 7][r] = v1.w;
        }
#pragma unroll
        for (int j = 0; j < 4; j++) {
            int fi = tid + j * 128;
            int kk = fi >> 4;
            int cc = (fi & 15) * 4;
            *(float4*)&ws[kk][cc] = *(const float4*)(W + (long long)(k0 + kk) * 64 + cc);
        }
        __syncthreads();
#pragma unroll
        for (int kk = 0; kk < 32; kk++) {
            float4 a = *(const float4*)&xsT[kk][ty * 4];
            const ull* bp = (const ull*)&ws[kk][tx * 4];
            ull b01 = bp[0], b23 = bp[1];
            ull a0 = dupf(a.x), a1 = dupf(a.y), a2 = dupf(a.z), a3 = dupf(a.w);
            ffma2(acc[0][0], a0, b01); ffma2(acc[0][1], a0, b23);
            ffma2(acc[1][0], a1, b01); ffma2(acc[1][1], a1, b23);
            ffma2(acc[2][0], a2, b01); ffma2(acc[2][1], a2, b23);
            ffma2(acc[3][0], a3, b01); ffma2(acc[3][1], a3, b23);
        }
        __syncthreads();
    }
#pragma unroll
    for (int i = 0; i < 4; i++) {
        long long row = row0 + ty * 4 + i;
        if (row < n) {
            float2 c0 = unpk(acc[i][0]), c1 = unpk(acc[i][1]);
            *(float4*)(C + row * 64 + tx * 4) = make_float4(c0.x, c0.y, c1.x, c1.y);
        }
    }
}

// ---------------- fused CSR gather: self loop + bias + agg + relu + stats ---
__global__ void k_gather(const float* __restrict__ xw, const float* __restrict__ bias,
                         float* __restrict__ out, long long n,
                         float* __restrict__ gsum, float* __restrict__ gsq) {
    __shared__ float ss[HC], sq[HC];
    int t = threadIdx.x;
    if (t < HC) { ss[t] = 0.f; sq[t] = 0.f; }
    __syncthreads();
    int grp = t >> 4;
    int ch  = (t & 15) * 4;
    long long node = blockIdx.x * 16LL + grp;
    if (node < n) {
        float dd = g_dis[node];
        float4 bv = *(const float4*)(bias + ch);
        float4 xv = *(const float4*)(xw + node * 64 + ch);
        float w0 = dd * dd;
        float4 acc = make_float4(bv.x + w0 * xv.x, bv.y + w0 * xv.y,
                                 bv.z + w0 * xv.z, bv.w + w0 * xv.w);
        int beg = g_rowptr[node], end = g_rowptr[node + 1];
        int i = beg;
        for (; i + 4 <= end; i += 4) {
            int s0 = g_csr[i], s1 = g_csr[i + 1], s2 = g_csr[i + 2], s3 = g_csr[i + 3];
            float n0 = dd * g_dis[s0], n1 = dd * g_dis[s1];
            float n2 = dd * g_dis[s2], n3 = dd * g_dis[s3];
            float4 v0 = *(const float4*)(xw + (long long)s0 * 64 + ch);
            float4 v1 = *(const float4*)(xw + (long long)s1 * 64 + ch);
            float4 v2 = *(const float4*)(xw + (long long)s2 * 64 + ch);
            float4 v3 = *(const float4*)(xw + (long long)s3 * 64 + ch);
            acc.x += n0 * v0.x + n1 * v1.x + n2 * v2.x + n3 * v3.x;
            acc.y += n0 * v0.y + n1 * v1.y + n2 * v2.y + n3 * v3.y;
            acc.z += n0 * v0.z + n1 * v1.z + n2 * v2.z + n3 * v3.z;
            acc.w += n0 * v0.w + n1 * v1.w + n2 * v2.w + n3 * v3.w;
        }
        for (; i < end; i++) {
            int s = g_csr[i];
            float nn = dd * g_dis[s];
            float4 v = *(const float4*)(xw + (long long)s * 64 + ch);
            acc.x += nn * v.x; acc.y += nn * v.y;
            acc.z += nn * v.z; acc.w += nn * v.w;
        }
        acc.x = fmaxf(acc.x, 0.f); acc.y = fmaxf(acc.y, 0.f);
        acc.z = fmaxf(acc.z, 0.f); acc.w = fmaxf(acc.w, 0.f);
        *(float4*)(out + node * 64 + ch) = acc;
        atomicAdd(&ss[ch + 0], acc.x); atomicAdd(&sq[ch + 0], acc.x * acc.x);
        atomicAdd(&ss[ch + 1], acc.y); atomicAdd(&sq[ch + 1], acc.y * acc.y);
        atomicAdd(&ss[ch + 2], acc.z); atomicAdd(&sq[ch + 2], acc.z * acc.z);
        atomicAdd(&ss[ch + 3], acc.w); atomicAdd(&sq[ch + 3], acc.w * acc.w);
    }
    __syncthreads();
    if (t < HC) { atomicAdd(&gsum[t], ss[t]); atomicAdd(&gsq[t], sq[t]); }
}

// ---------------- fused BN2 + mean pool + MLP: one block per graph -----------
__global__ void k_poolmlp(const float* __restrict__ buf, const float* __restrict__ gsum,
                          const float* __restrict__ gsq, const float* __restrict__ gamma,
                          const float* __restrict__ beta, const void* batch,
                          float invN, long long n,
                          const float* __restrict__ fw1, const float* __restrict__ fb1,
                          const float* __restrict__ fw2, const float* __restrict__ fb2,
                          const float* __restrict__ fw3, const float* __restrict__ fb3,
                          const float* __restrict__ fw4, const float* __restrict__ fb4,
                          const float* __restrict__ ow,  const float* __restrict__ ob,
                          float* __restrict__ out) {
    __shared__ float sc[64], sh[64], p[64], part[256];
    __shared__ float a1[128], a2[64], a3[32], a4[16];
    __shared__ int seg[2];
    int g = blockIdx.x, t = threadIdx.x;
    if (t < 64) {
        float m   = gsum[t] * invN;
        float var = gsq[t] * invN - m * m;
        float s   = rsqrtf(var + EPSV) * gamma[t];
        sc[t] = s; sh[t] = beta[t] - m * s;
    }
    if (t < 2) {   // lower_bound(batch, g + t): batch is sorted
        long long target = g + t;
        long long lo = 0, hi = n;
        while (lo < hi) {
            long long mid = (lo + hi) >> 1;
            if (ld_idx(batch, mid) < target) lo = mid + 1; else hi = mid;
        }
        seg[t] = (int)lo;
    }
    __syncthreads();
    int beg = seg[0], end = seg[1];
    int c = t & 63, grp = t >> 6;
    float s = 0.f;
    for (long long node = beg + grp; node < end; node += 4)
        s += buf[node * 64 + c] * sc[c] + sh[c];
    part[t] = s;
    __syncthreads();
    if (t < 64) {
        float cnt = (float)(end - beg);
        p[t] = (part[t] + part[t + 64] + part[t + 128] + part[t + 192]) / fmaxf(cnt, 1.f);
    }
    __syncthreads();
    if (t < 128) {
        float a = fb1[t];
#pragma unroll 8
        for (int k = 0; k < 64; k++) a += p[k] * fw1[k * 128 + t];
        a1[t] = fmaxf(a, 0.f);
    }
    __syncthreads();
    if (t < 64) {
        float a = fb2[t];
#pragma unroll 8
        for (int k = 0; k < 128; k++) a += a1[k] * fw2[k * 64 + t];
        a2[t] = fmaxf(a, 0.f);
    }
    __syncthreads();
    if (t < 32) {
        float a = fb3[t];
#pragma unroll 8
        for (int k = 0; k < 64; k++) a += a2[k] * fw3[k * 32 + t];
        a3[t] = fmaxf(a, 0.f);
    }
    __syncthreads();
    if (t < 16) {
        float a = fb4[t];
#pragma unroll
        for (int k = 0; k < 32; k++) a += a3[k] * fw4[k * 16 + t];
        a4[t] = fmaxf(a, 0.f);
    }
    __syncthreads();
    if (t < 2) {
        float a = ob[t];
#pragma unroll
        for (int k = 0; k < 16; k++) a += a4[k] * ow[k * 2 + t];
        out[g * 2 + t] = a;
    }
}

// ---------------- launcher ------------------------------------------------------
extern "C" void kernel_launch(void* const* d_in, const int* in_sizes, int n_in,
                              void* d_out, int out_size) {
    const float* x   = (const float*)d_in[0];
    const void*  ei  = d_in[1];
    const void*  bat = d_in[2];
    const float* w1  = (const float*)d_in[3];
    const float* b1  = (const float*)d_in[4];
    const float* w2  = (const float*)d_in[5];
    const float* b2  = (const float*)d_in[6];
    const float* g1  = (const float*)d_in[7];
    const float* be1 = (const float*)d_in[8];
    const float* g2  = (const float*)d_in[9];
    const float* be2 = (const float*)d_in[10];
    const float* fw1 = (const float*)d_in[11];
    const float* fb1 = (const float*)d_in[12];
    const float* fw2 = (const float*)d_in[13];
    const float* fb2 = (const float*)d_in[14];
    const float* fw3 = (const float*)d_in[15];
    const float* fb3 = (const float*)d_in[16];
    const float* fw4 = (const float*)d_in[17];
    const float* fb4 = (const float*)d_in[18];
    const float* ow  = (const float*)d_in[19];
    const float* ob  = (const float*)d_in[20];
    float* out = (float*)d_out;

    const long long N = in_sizes[0] / 256;   // C = 256
    const long long E = in_sizes[1] / 2;
    const int       G = out_size / 2;
    const float invN = 1.0f / (float)N;

    float *bufA, *bufB, *sum1, *sq1, *sum2, *sq2;
    cudaGetSymbolAddress((void**)&bufA, g_bufA);
    cudaGetSymbolAddress((void**)&bufB, g_bufB);
    cudaGetSymbolAddress((void**)&sum1, g_sum1);
    cudaGetSymbolAddress((void**)&sq1,  g_sq1);
    cudaGetSymbolAddress((void**)&sum2, g_sum2);
    cudaGetSymbolAddress((void**)&sq2,  g_sq2);

    const int TB = 256;
    const int gN    = (int)((N + TB - 1) / TB);
    const int gE    = (int)((E + TB - 1) / TB);
    const int gGemm = (int)((N + 31) / 32);
    const int gGath = (int)((N + 15) / 16);
    const int nb    = (int)((N + 255) / 256);

    // ---- index dtype + CSR build ----
    k_zero<<<gN, TB>>>(ei, N);
    k_hist<<<gE, TB>>>(ei, E);
    k_scan1<<<nb, 256>>>(N);
    k_scan2<<<1, 512>>>(nb);
    k_scan3<<<gN, TB>>>(N, (int)E);
    k_scatter<<<gE, TB>>>(ei, E);

    // ---- GCN layer 1 ----
    k_gemm<256, false><<<gGemm, 128>>>(x, w1, bufA, N, nullptr, nullptr, nullptr, nullptr, 0.f);
    k_gather<<<gGath, 256>>>(bufA, b1, bufB, N, sum1, sq1);

    // ---- GCN layer 2 (BN1 folded into A-load) ----
    k_gemm<64, true><<<gGemm, 128>>>(bufB, w2, bufA, N, sum1, sq1, g1, be1, invN);
    k_gather<<<gGath, 256>>>(bufA, b2, bufB, N, sum2, sq2);

    // ---- fused BN2 + pool + MLP head ----
    k_poolmlp<<<G, 256>>>(bufB, sum2, sq2, g2, be2, bat, invN, N,
                          fw1, fb1, fw2, fb2, fw3, fb3, fw4, fb4, ow, ob, out);
}

// round 8
// speedup vs baseline: 1.3609x; 1.3303x over previous
#include <cuda_runtime.h>

typedef unsigned long long ull;

// ---------------- problem constants (shapes fixed by the dataset) -----------
#define MAXN 100000
#define MAXE 3342336
#define HC   64
#define MAXG 512
#define EPSV 1e-5f

// ---------------- device scratch (static; no allocation) --------------------
__device__ float g_bufA[MAXN * HC];      // projected features (xW)
__device__ float g_bufB[MAXN * HC];      // aggregated features (h)
__device__ float g_dis[MAXN];            // rsqrt(deg)
__device__ int   g_deg[MAXN];            // in-degree (w/o self loop)
__device__ int   g_rowptr[MAXN + 1];
__device__ int   g_cursor[MAXN];
__device__ int   g_csr[MAXE];            // src ids grouped by dst
__device__ int   g_bsum[512];
__device__ int   g_boff[512];
__device__ float g_sum1[HC], g_sq1[HC], g_sum2[HC], g_sq2[HC];
__device__ float g_pool[MAXG * HC];
__device__ float g_cnt[MAXG];
__device__ int   g_is64;

// ---------------- dtype-agnostic index load ---------------------------------
__device__ __forceinline__ long long ld_idx(const void* p, long long i) {
    if (g_is64) return ((const long long*)p)[i];
    return (long long)((const int*)p)[i];
}

__global__ void k_detect(const void* ei, long long n_nodes) {
    const long long* p = (const long long*)ei;
    int ok = 1;
    for (int i = 0; i < 64; i++) {
        long long v = p[i];
        if (v < 0 || v >= n_nodes) { ok = 0; break; }
    }
    g_is64 = ok;
}

// ---------------- packed f32x2 helpers (Blackwell) --------------------------
__device__ __forceinline__ ull dupf(float a) {
    ull r; unsigned int u = __float_as_uint(a);
    asm("mov.b64 %0, {%1, %1};" : "=l"(r) : "r"(u));
    return r;
}
__device__ __forceinline__ void ffma2(ull& d, ull a, ull b) {
    asm("fma.rn.f32x2 %0, %1, %2, %0;" : "+l"(d) : "l"(a), "l"(b));
}
__device__ __forceinline__ float2 unpk(ull v) {
    unsigned int lo, hi;
    asm("mov.b64 {%0, %1}, %2;" : "=r"(lo), "=r"(hi) : "l"(v));
    return make_float2(__uint_as_float(lo), __uint_as_float(hi));
}

// ---------------- init: zero deg/pool/cnt/bn sums ----------------------------
__global__ void k_zero(long long n) {
    long long i = blockIdx.x * (long long)blockDim.x + threadIdx.x;
    if (i < n)          g_deg[i] = 0;
    if (i < MAXG * HC)  g_pool[i] = 0.0f;
    if (i < MAXG)       g_cnt[i] = 0.0f;
    if (i < HC) { g_sum1[i] = 0.f; g_sq1[i] = 0.f; g_sum2[i] = 0.f; g_sq2[i] = 0.f; }
}

__global__ void k_hist(const void* ei, long long E) {
    long long e = blockIdx.x * (long long)blockDim.x + threadIdx.x;
    if (e >= E) return;
    atomicAdd(&g_deg[ld_idx(ei, E + e)], 1);
}

// ---------------- exclusive scan over g_deg ------------------------------------
__global__ void k_scan1(long long n) {
    __shared__ int wsum[8];
    int t = threadIdx.x;
    long long i = blockIdx.x * 256LL + t;
    int v = (i < n) ? g_deg[i] : 0;
    int x = v;
#pragma unroll
    for (int o = 1; o < 32; o <<= 1) {
        int y = __shfl_up_sync(~0u, x, o);
        if ((t & 31) >= o) x += y;
    }
    if ((t & 31) == 31) wsum[t >> 5] = x;
    __syncthreads();
    if (t < 8) {
        int y = wsum[t];
#pragma unroll
        for (int o = 1; o < 8; o <<= 1) {
            int z = __shfl_up_sync(0xff, y, o);
            if (t >= o) y += z;
        }
        wsum[t] = y;
    }
    __syncthreads();
    int base = (t >= 32) ? wsum[(t >> 5) - 1] : 0;
    int incl = x + base;
    if (i < n) g_rowptr[i] = incl - v;
    if (t == 255) g_bsum[blockIdx.x] = incl;
}

__global__ void k_scan2(int nb) {
    __shared__ int wsum[16];
    int t = threadIdx.x;
    int v = (t < nb) ? g_bsum[t] : 0;
    int x = v;
#pragma unroll
    for (int o = 1; o < 32; o <<= 1) {
        int y = __shfl_up_sync(~0u, x, o);
        if ((t & 31) >= o) x += y;
    }
    if ((t & 31) == 31) wsum[t >> 5] = x;
    __syncthreads();
    if (t < 16) {
        int y = wsum[t];
#pragma unroll
        for (int o = 1; o < 16; o <<= 1) {
            int z = __shfl_up_sync(0xffff, y, o);
            if (t >= o) y += z;
        }
        wsum[t] = y;
    }
    __syncthreads();
    int base = (t >= 32) ? wsum[(t >> 5) - 1] : 0;
    g_boff[t] = x + base - v;
}

__global__ void k_scan3(long long n, int E) {
    long long i = blockIdx.x * (long long)blockDim.x + threadIdx.x;
    if (i < n) {
        int rp = g_rowptr[i] + g_boff[i >> 8];
        g_rowptr[i] = rp;
        g_cursor[i] = rp;
        g_dis[i] = rsqrtf((float)(g_deg[i] + 1));
    }
    if (i == 0) g_rowptr[n] = E;
}

__global__ void k_scatter(const void* ei, long long E) {
    long long e = blockIdx.x * (long long)blockDim.x + threadIdx.x;
    if (e >= E) return;
    long long s = ld_idx(ei, e);
    long long d = ld_idx(ei, E + e);
    int pos = atomicAdd(&g_cursor[d], 1);
    g_csr[pos] = (int)s;
}

// ---------------- GEMM: C[N,64] = A[N,K] @ W[K,64] ---------------------------
// 128 threads, block tile 64x64, thread tile 4x8 (8 rows x 4 cols),
// packed f32x2 accumulators. Pad 68 keeps every row 16B-aligned (68*4=272).
template <int K>
__global__ void k_gemm(const float* __restrict__ A, const float* __restrict__ W,
                       float* __restrict__ C, long long n) {
    __shared__ __align__(16) float xsT[32][68];   // [k][row]; 272B row stride
    __shared__ __align__(16) float ws[32][64];    // [k][col]
    const int tid = threadIdx.x;
    const int tx = tid & 15;        // col group: 4 cols
    const int ty = tid >> 4;        // row group: 8 rows
    const long long row0 = (long long)blockIdx.x * 64;
    ull acc[8][2] = {};

    const int lrow = tid >> 1;              // 0..63  row this thread loads
    const int lko  = (tid & 1) * 16;        // k-offset 0 or 16
    const long long grow = row0 + lrow;
    const bool rok = grow < n;

    for (int k0 = 0; k0 < K; k0 += 32) {
        // ---- load x tile (64 rows x 32 k), 16 k-values per thread ----
        float4 xv[4];
        if (rok) {
            const float* src = A + grow * (long long)K + k0 + lko;
#pragma unroll
            for (int q = 0; q < 4; q++) xv[q] = *(const float4*)(src + q * 4);
        } else {
#pragma unroll
            for (int q = 0; q < 4; q++) xv[q] = make_float4(0.f, 0.f, 0.f, 0.f);
        }
        // ---- load W tile (32 k x 64 cols), 4 float4 per thread ----
        float4 wv[4];
#pragma unroll
        for (int j = 0; j < 4; j++) {
            int fi = tid + j * 128;
            int kk = fi >> 4;
            int cc = (fi & 15) * 4;
            wv[j] = *(const float4*)(W + (long long)(k0 + kk) * 64 + cc);
        }
        __syncthreads();   // previous iteration's compute done
#pragma unroll
        for (int q = 0; q < 4; q++) {
            xsT[lko + q * 4 + 0][lrow] = xv[q].x;
            xsT[lko + q * 4 + 1][lrow] = xv[q].y;
            xsT[lko + q * 4 + 2][lrow] = xv[q].z;
            xsT[lko + q * 4 + 3][lrow] = xv[q].w;
        }
#pragma unroll
        for (int j = 0; j < 4; j++) {
            int fi = tid + j * 128;
            int kk = fi >> 4;
            int cc = (fi & 15) * 4;
            *(float4*)&ws[kk][cc] = wv[j];
        }
        __syncthreads();
#pragma unroll
        for (int kk = 0; kk < 32; kk++) {
            float4 a0 = *(const float4*)&xsT[kk][ty * 8];
            float4 a1 = *(const float4*)&xsT[kk][ty * 8 + 4];
            const ull* bp = (const ull*)&ws[kk][tx * 4];
            ull b01 = bp[0], b23 = bp[1];
            ull a;
            a = dupf(a0.x); ffma2(acc[0][0], a, b01); ffma2(acc[0][1], a, b23);
            a = dupf(a0.y); ffma2(acc[1][0], a, b01); ffma2(acc[1][1], a, b23);
            a = dupf(a0.z); ffma2(acc[2][0], a, b01); ffma2(acc[2][1], a, b23);
            a = dupf(a0.w); ffma2(acc[3][0], a, b01); ffma2(acc[3][1], a, b23);
            a = dupf(a1.x); ffma2(acc[4][0], a, b01); ffma2(acc[4][1], a, b23);
            a = dupf(a1.y); ffma2(acc[5][0], a, b01); ffma2(acc[5][1], a, b23);
            a = dupf(a1.z); ffma2(acc[6][0], a, b01); ffma2(acc[6][1], a, b23);
            a = dupf(a1.w); ffma2(acc[7][0], a, b01); ffma2(acc[7][1], a, b23);
        }
        __syncthreads();
    }
#pragma unroll
    for (int i = 0; i < 8; i++) {
        long long row = row0 + ty * 8 + i;
        if (row < n) {
            float2 c0 = unpk(acc[i][0]), c1 = unpk(acc[i][1]);
            *(float4*)(C + row * 64 + tx * 4) = make_float4(c0.x, c0.y, c1.x, c1.y);
        }
    }
}

// ---------------- fused CSR gather: self loop + bias + agg + relu + stats ---
__global__ void k_gather(const float* __restrict__ xw, const float* __restrict__ bias,
                         float* __restrict__ out, long long n,
                         float* __restrict__ gsum, float* __restrict__ gsq) {
    __shared__ float ss[HC], sq[HC];
    int t = threadIdx.x;
    if (t < HC) { ss[t] = 0.f; sq[t] = 0.f; }
    __syncthreads();
    int grp = t >> 4;
    int ch  = (t & 15) * 4;
    long long node = blockIdx.x * 16LL + grp;
    if (node < n) {
        float dd = g_dis[node];
        float4 bv = *(const float4*)(bias + ch);
        float4 xv = *(const float4*)(xw + node * 64 + ch);
        float w0 = dd * dd;
        float4 acc = make_float4(bv.x + w0 * xv.x, bv.y + w0 * xv.y,
                                 bv.z + w0 * xv.z, bv.w + w0 * xv.w);
        int beg = g_rowptr[node], end = g_rowptr[node + 1];
        int i = beg;
        for (; i + 4 <= end; i += 4) {
            int s0 = g_csr[i], s1 = g_csr[i + 1], s2 = g_csr[i + 2], s3 = g_csr[i + 3];
            float n0 = dd * g_dis[s0], n1 = dd * g_dis[s1];
            float n2 = dd * g_dis[s2], n3 = dd * g_dis[s3];
            float4 v0 = *(const float4*)(xw + (long long)s0 * 64 + ch);
            float4 v1 = *(const float4*)(xw + (long long)s1 * 64 + ch);
            float4 v2 = *(const float4*)(xw + (long long)s2 * 64 + ch);
            float4 v3 = *(const float4*)(xw + (long long)s3 * 64 + ch);
            acc.x += n0 * v0.x + n1 * v1.x + n2 * v2.x + n3 * v3.x;
            acc.y += n0 * v0.y + n1 * v1.y + n2 * v2.y + n3 * v3.y;
            acc.z += n0 * v0.z + n1 * v1.z + n2 * v2.z + n3 * v3.z;
            acc.w += n0 * v0.w + n1 * v1.w + n2 * v2.w + n3 * v3.w;
        }
        for (; i < end; i++) {
            int s = g_csr[i];
            float nn = dd * g_dis[s];
            float4 v = *(const float4*)(xw + (long long)s * 64 + ch);
            acc.x += nn * v.x; acc.y += nn * v.y;
            acc.z += nn * v.z; acc.w += nn * v.w;
        }
        acc.x = fmaxf(acc.x, 0.f); acc.y = fmaxf(acc.y, 0.f);
        acc.z = fmaxf(acc.z, 0.f); acc.w = fmaxf(acc.w, 0.f);
        *(float4*)(out + node * 64 + ch) = acc;
        atomicAdd(&ss[ch + 0], acc.x); atomicAdd(&sq[ch + 0], acc.x * acc.x);
        atomicAdd(&ss[ch + 1], acc.y); atomicAdd(&sq[ch + 1], acc.y * acc.y);
        atomicAdd(&ss[ch + 2], acc.z); atomicAdd(&sq[ch + 2], acc.z * acc.z);
        atomicAdd(&ss[ch + 3], acc.w); atomicAdd(&sq[ch + 3], acc.w * acc.w);
    }
    __syncthreads();
    if (t < HC) { atomicAdd(&gsum[t], ss[t]); atomicAdd(&gsq[t], sq[t]); }
}

// ---------------- BN apply (in place) ----------------------------------------
__global__ void k_bn(float* __restrict__ buf, const float* __restrict__ gsum,
                     const float* __restrict__ gsq, const float* __restrict__ gamma,
                     const float* __restrict__ beta, float invN, long long n64) {
    long long idx = blockIdx.x * (long long)blockDim.x + threadIdx.x;
    if (idx >= n64) return;
    int c = (int)(idx & 63);
    float m   = gsum[c] * invN;
    float var = gsq[c] * invN - m * m;
    float sc  = rsqrtf(var + EPSV) * gamma[c];
    buf[idx] = (buf[idx] - m) * sc + beta[c];
}

// ---------------- BN apply + global mean pool accumulation ------------------
__global__ void k_bnpool(const float* __restrict__ buf, const float* __restrict__ gsum,
                         const float* __restrict__ gsq, const float* __restrict__ gamma,
                         const float* __restrict__ beta, const void* batch,
                         float invN, long long n64) {
    long long idx = blockIdx.x * (long long)blockDim.x + threadIdx.x;
    if (idx >= n64) return;
    long long i = idx >> 6;
    int c = (int)(idx & 63);
    float m   = gsum[c] * invN;
    float var = gsq[c] * invN - m * m;
    float sc  = rsqrtf(var + EPSV) * gamma[c];
    float val = (buf[idx] - m) * sc + beta[c];
    long long b = ld_idx(batch, i);
    atomicAdd(&g_pool[b * 64 + c], val);
    if (c == 0) atomicAdd(&g_cnt[b], 1.0f);
}

// ---------------- fused MLP head: one block per graph ------------------------
__global__ void k_mlp(const float* __restrict__ fw1, const float* __restrict__ fb1,
                      const float* __restrict__ fw2, const float* __restrict__ fb2,
                      const float* __restrict__ fw3, const float* __restrict__ fb3,
                      const float* __restrict__ fw4, const float* __restrict__ fb4,
                      const float* __restrict__ ow,  const float* __restrict__ ob,
                      float* __restrict__ out) {
    __shared__ float p[64], a1[128], a2[64], a3[32], a4[16];
    int g = blockIdx.x, t = threadIdx.x;
    float inv = 1.0f / fmaxf(g_cnt[g], 1.0f);
    if (t < 64) p[t] = g_pool[g * 64 + t] * inv;
    __syncthreads();
    if (t < 128) {
        float a = fb1[t];
#pragma unroll 8
        for (int k = 0; k < 64; k++) a += p[k] * fw1[k * 128 + t];
        a1[t] = fmaxf(a, 0.f);
    }
    __syncthreads();
    if (t < 64) {
        float a = fb2[t];
#pragma unroll 8
        for (int k = 0; k < 128; k++) a += a1[k] * fw2[k * 64 + t];
        a2[t] = fmaxf(a, 0.f);
    }
    __syncthreads();
    if (t < 32) {
        float a = fb3[t];
#pragma unroll 8
        for (int k = 0; k < 64; k++) a += a2[k] * fw3[k * 32 + t];
        a3[t] = fmaxf(a, 0.f);
    }
    __syncthreads();
    if (t < 16) {
        float a = fb4[t];
#pragma unroll
        for (int k = 0; k < 32; k++) a += a3[k] * fw4[k * 16 + t];
        a4[t] = fmaxf(a, 0.f);
    }
    __syncthreads();
    if (t < 2) {
        float a = ob[t];
#pragma unroll
        for (int k = 0; k < 16; k++) a += a4[k] * ow[k * 2 + t];
        out[g * 2 + t] = a;
    }
}

// ---------------- launcher ------------------------------------------------------
extern "C" void kernel_launch(void* const* d_in, const int* in_sizes, int n_in,
                              void* d_out, int out_size) {
    const float* x   = (const float*)d_in[0];
    const void*  ei  = d_in[1];
    const void*  bat = d_in[2];
    const float* w1  = (const float*)d_in[3];
    const float* b1  = (const float*)d_in[4];
    const float* w2  = (const float*)d_in[5];
    const float* b2  = (const float*)d_in[6];
    const float* g1  = (const float*)d_in[7];
    const float* be1 = (const float*)d_in[8];
    const float* g2  = (const float*)d_in[9];
    const float* be2 = (const float*)d_in[10];
    const float* fw1 = (const float*)d_in[11];
    const float* fb1 = (const float*)d_in[12];
    const float* fw2 = (const float*)d_in[13];
    const float* fb2 = (const float*)d_in[14];
    const float* fw3 = (const float*)d_in[15];
    const float* fb3 = (const float*)d_in[16];
    const float* fw4 = (const float*)d_in[17];
    const float* fb4 = (const float*)d_in[18];
    const float* ow  = (const float*)d_in[19];
    const float* ob  = (const float*)d_in[20];
    float* out = (float*)d_out;

    const long long N = in_sizes[0] / 256;   // C = 256
    const long long E = in_sizes[1] / 2;
    const int       G = out_size / 2;
    const long long n64 = N * 64;
    const float invN = 1.0f / (float)N;

    float *bufA, *bufB, *sum1, *sq1, *sum2, *sq2;
    cudaGetSymbolAddress((void**)&bufA, g_bufA);
    cudaGetSymbolAddress((void**)&bufB, g_bufB);
    cudaGetSymbolAddress((void**)&sum1, g_sum1);
    cudaGetSymbolAddress((void**)&sq1,  g_sq1);
    cudaGetSymbolAddress((void**)&sum2, g_sum2);
    cudaGetSymbolAddress((void**)&sq2,  g_sq2);

    const int TB = 256;
    const int gN    = (int)((N + TB - 1) / TB);
    const int gE    = (int)((E + TB - 1) / TB);
    const int gN64  = (int)((n64 + TB - 1) / TB);
    const int gGemm = (int)((N + 63) / 64);
    const int gGath = (int)((N + 15) / 16);
    const int nb    = (int)((N + 255) / 256);

    // ---- index dtype + CSR build ----
    k_detect<<<1, 1>>>(ei, N);
    k_zero<<<gN, TB>>>(N);
    k_hist<<<gE, TB>>>(ei, E);
    k_scan1<<<nb, 256>>>(N);
    k_scan2<<<1, 512>>>(nb);
    k_scan3<<<gN, TB>>>(N, (int)E);
    k_scatter<<<gE, TB>>>(ei, E);

    // ---- GCN layer 1 ----
    k_gemm<256><<<gGemm, 128>>>(x, w1, bufA, N);
    k_gather<<<gGath, 256>>>(bufA, b1, bufB, N, sum1, sq1);
    k_bn<<<gN64, TB>>>(bufB, sum1, sq1, g1, be1, invN, n64);

    // ---- GCN layer 2 ----
    k_gemm<64><<<gGemm, 128>>>(bufB, w2, bufA, N);
    k_gather<<<gGath, 256>>>(bufA, b2, bufB, N, sum2, sq2);
    k_bnpool<<<gN64, TB>>>(bufB, sum2, sq2, g2, be2, bat, invN, n64);

    // ---- MLP head ----
    k_mlp<<<G, 128>>>(fw1, fb1, fw2, fb2, fw3, fb3, fw4, fb4, ow, ob, out);
}

// round 9
// speedup vs baseline: 1.4347x; 1.0542x over previous
#include <cuda_runtime.h>

typedef unsigned long long ull;

// ---------------- problem constants (shapes fixed by the dataset) -----------
#define MAXN 100000
#define MAXE 3342336
#define HC   64
#define MAXG 512
#define EPSV 1e-5f

// ---------------- device scratch (static; no allocation) --------------------
__device__ float g_bufA[MAXN * HC];      // projected features (xW)
__device__ float g_bufB[MAXN * HC];      // aggregated features (h)
__device__ float g_dis[MAXN];            // rsqrt(deg)
__device__ int   g_deg[MAXN];            // in-degree (w/o self loop)
__device__ int   g_rowptr[MAXN + 1];
__device__ int   g_cursor[MAXN];
__device__ int   g_csr[MAXE];            // src ids grouped by dst
__device__ int   g_bsum[512];
__device__ int   g_boff[512];
__device__ float g_sum1[HC], g_sq1[HC], g_sum2[HC], g_sq2[HC];
__device__ float g_pool[MAXG * HC];
__device__ float g_cnt[MAXG];
__device__ int   g_is64;

// ---------------- host-side stream/event objects (created pre-main) ---------
static cudaStream_t hx_s2;
static cudaEvent_t  hx_fork, hx_join;
namespace {
struct HXInit {
    HXInit() {
        cudaStreamCreateWithFlags(&hx_s2, cudaStreamNonBlocking);
        cudaEventCreateWithFlags(&hx_fork, cudaEventDisableTiming);
        cudaEventCreateWithFlags(&hx_join, cudaEventDisableTiming);
    }
};
static HXInit hx_init;
}

// ---------------- dtype-agnostic index load ---------------------------------
__device__ __forceinline__ long long ld_idx(const void* p, long long i) {
    if (g_is64) return ((const long long*)p)[i];
    return (long long)((const int*)p)[i];
}

__global__ void k_detect(const void* ei, long long n_nodes) {
    const long long* p = (const long long*)ei;
    int ok = 1;
    for (int i = 0; i < 64; i++) {
        long long v = p[i];
        if (v < 0 || v >= n_nodes) { ok = 0; break; }
    }
    g_is64 = ok;
}

// ---------------- packed f32x2 helpers (Blackwell) --------------------------
__device__ __forceinline__ ull dupf(float a) {
    ull r; unsigned int u = __float_as_uint(a);
    asm("mov.b64 %0, {%1, %1};" : "=l"(r) : "r"(u));
    return r;
}
__device__ __forceinline__ void ffma2(ull& d, ull a, ull b) {
    asm("fma.rn.f32x2 %0, %1, %2, %0;" : "+l"(d) : "l"(a), "l"(b));
}
__device__ __forceinline__ float2 unpk(ull v) {
    unsigned int lo, hi;
    asm("mov.b64 {%0, %1}, %2;" : "=r"(lo), "=r"(hi) : "l"(v));
    return make_float2(__uint_as_float(lo), __uint_as_float(hi));
}

// ---------------- init: zero deg/pool/cnt/bn sums ----------------------------
__global__ void k_zero(long long n) {
    long long i = blockIdx.x * (long long)blockDim.x + threadIdx.x;
    if (i < n)          g_deg[i] = 0;
    if (i < MAXG * HC)  g_pool[i] = 0.0f;
    if (i < MAXG)       g_cnt[i] = 0.0f;
    if (i < HC) { g_sum1[i] = 0.f; g_sq1[i] = 0.f; g_sum2[i] = 0.f; g_sq2[i] = 0.f; }
}

__global__ void k_hist(const void* ei, long long E) {
    long long e = blockIdx.x * (long long)blockDim.x + threadIdx.x;
    if (e >= E) return;
    atomicAdd(&g_deg[ld_idx(ei, E + e)], 1);
}

// ---------------- exclusive scan over g_deg ------------------------------------
__global__ void k_scan1(long long n) {
    __shared__ int wsum[8];
    int t = threadIdx.x;
    long long i = blockIdx.x * 256LL + t;
    int v = (i < n) ? g_deg[i] : 0;
    int x = v;
#pragma unroll
    for (int o = 1; o < 32; o <<= 1) {
        int y = __shfl_up_sync(~0u, x, o);
        if ((t & 31) >= o) x += y;
    }
    if ((t & 31) == 31) wsum[t >> 5] = x;
    __syncthreads();
    if (t < 8) {
        int y = wsum[t];
#pragma unroll
        for (int o = 1; o < 8; o <<= 1) {
            int z = __shfl_up_sync(0xff, y, o);
            if (t >= o) y += z;
        }
        wsum[t] = y;
    }
    __syncthreads();
    int base = (t >= 32) ? wsum[(t >> 5) - 1] : 0;
    int incl = x + base;
    if (i < n) g_rowptr[i] = incl - v;
    if (t == 255) g_bsum[blockIdx.x] = incl;
}

__global__ void k_scan2(int nb) {
    __shared__ int wsum[16];
    int t = threadIdx.x;
    int v = (t < nb) ? g_bsum[t] : 0;
    int x = v;
#pragma unroll
    for (int o = 1; o < 32; o <<= 1) {
        int y = __shfl_up_sync(~0u, x, o);
        if ((t & 31) >= o) x += y;
    }
    if ((t & 31) == 31) wsum[t >> 5] = x;
    __syncthreads();
    if (t < 16) {
        int y = wsum[t];
#pragma unroll
        for (int o = 1; o < 16; o <<= 1) {
            int z = __shfl_up_sync(0xffff, y, o);
            if (t >= o) y += z;
        }
        wsum[t] = y;
    }
    __syncthreads();
    int base = (t >= 32) ? wsum[(t >> 5) - 1] : 0;
    g_boff[t] = x + base - v;
}

__global__ void k_scan3(long long n, int E) {
    long long i = blockIdx.x * (long long)blockDim.x + threadIdx.x;
    if (i < n) {
        int rp = g_rowptr[i] + g_boff[i >> 8];
        g_rowptr[i] = rp;
        g_cursor[i] = rp;
        g_dis[i] = rsqrtf((float)(g_deg[i] + 1));
    }
    if (i == 0) g_rowptr[n] = E;
}

__global__ void k_scatter(const void* ei, long long E) {
    long long e = blockIdx.x * (long long)blockDim.x + threadIdx.x;
    if (e >= E) return;
    long long s = ld_idx(ei, e);
    long long d = ld_idx(ei, E + e);
    int pos = atomicAdd(&g_cursor[d], 1);
    g_csr[pos] = (int)s;
}

// ---------------- GEMM: C[N,64] = A[N,K] @ W[K,64] ---------------------------
// 128 threads, block tile 64x64, thread tile 4x8 (8 rows x 4 cols),
// packed f32x2 accumulators. Pad 68 keeps every row 16B-aligned (68*4=272).
template <int K>
__global__ void k_gemm(const float* __restrict__ A, const float* __restrict__ W,
                       float* __restrict__ C, long long n) {
    __shared__ __align__(16) float xsT[32][68];   // [k][row]; 272B row stride
    __shared__ __align__(16) float ws[32][64];    // [k][col]
    const int tid = threadIdx.x;
    const int tx = tid & 15;        // col group: 4 cols
    const int ty = tid >> 4;        // row group: 8 rows
    const long long row0 = (long long)blockIdx.x * 64;
    ull acc[8][2] = {};

    const int lrow = tid >> 1;              // 0..63  row this thread loads
    const int lko  = (tid & 1) * 16;        // k-offset 0 or 16
    const long long grow = row0 + lrow;
    const bool rok = grow < n;

    for (int k0 = 0; k0 < K; k0 += 32) {
        // ---- load x tile (64 rows x 32 k), 16 k-values per thread ----
        float4 xv[4];
        if (rok) {
            const float* src = A + grow * (long long)K + k0 + lko;
#pragma unroll
            for (int q = 0; q < 4; q++) xv[q] = *(const float4*)(src + q * 4);
        } else {
#pragma unroll
            for (int q = 0; q < 4; q++) xv[q] = make_float4(0.f, 0.f, 0.f, 0.f);
        }
        // ---- load W tile (32 k x 64 cols), 4 float4 per thread ----
        float4 wv[4];
#pragma unroll
        for (int j = 0; j < 4; j++) {
            int fi = tid + j * 128;
            int kk = fi >> 4;
            int cc = (fi & 15) * 4;
            wv[j] = *(const float4*)(W + (long long)(k0 + kk) * 64 + cc);
        }
        __syncthreads();   // previous iteration's compute done
#pragma unroll
        for (int q = 0; q < 4; q++) {
            xsT[lko + q * 4 + 0][lrow] = xv[q].x;
            xsT[lko + q * 4 + 1][lrow] = xv[q].y;
            xsT[lko + q * 4 + 2][lrow] = xv[q].z;
            xsT[lko + q * 4 + 3][lrow] = xv[q].w;
        }
#pragma unroll
        for (int j = 0; j < 4; j++) {
            int fi = tid + j * 128;
            int kk = fi >> 4;
            int cc = (fi & 15) * 4;
            *(float4*)&ws[kk][cc] = wv[j];
        }
        __syncthreads();
#pragma unroll
        for (int kk = 0; kk < 32; kk++) {
            float4 a0 = *(const float4*)&xsT[kk][ty * 8];
            float4 a1 = *(const float4*)&xsT[kk][ty * 8 + 4];
            const ull* bp = (const ull*)&ws[kk][tx * 4];
            ull b01 = bp[0], b23 = bp[1];
            ull a;
            a = dupf(a0.x); ffma2(acc[0][0], a, b01); ffma2(acc[0][1], a, b23);
            a = dupf(a0.y); ffma2(acc[1][0], a, b01); ffma2(acc[1][1], a, b23);
            a = dupf(a0.z); ffma2(acc[2][0], a, b01); ffma2(acc[2][1], a, b23);
            a = dupf(a0.w); ffma2(acc[3][0], a, b01); ffma2(acc[3][1], a, b23);
            a = dupf(a1.x); ffma2(acc[4][0], a, b01); ffma2(acc[4][1], a, b23);
            a = dupf(a1.y); ffma2(acc[5][0], a, b01); ffma2(acc[5][1], a, b23);
            a = dupf(a1.z); ffma2(acc[6][0], a, b01); ffma2(acc[6][1], a, b23);
            a = dupf(a1.w); ffma2(acc[7][0], a, b01); ffma2(acc[7][1], a, b23);
        }
        __syncthreads();
    }
#pragma unroll
    for (int i = 0; i < 8; i++) {
        long long row = row0 + ty * 8 + i;
        if (row < n) {
            float2 c0 = unpk(acc[i][0]), c1 = unpk(acc[i][1]);
            *(float4*)(C + row * 64 + tx * 4) = make_float4(c0.x, c0.y, c1.x, c1.y);
        }
    }
}

// ---------------- fused CSR gather: self loop + bias + agg + relu + stats ---
__global__ void k_gather(const float* __restrict__ xw, const float* __restrict__ bias,
                         float* __restrict__ out, long long n,
                         float* __restrict__ gsum, float* __restrict__ gsq) {
    __shared__ float ss[HC], sq[HC];
    int t = threadIdx.x;
    if (t < HC) { ss[t] = 0.f; sq[t] = 0.f; }
    __syncthreads();
    int grp = t >> 4;
    int ch  = (t & 15) * 4;
    long long node = blockIdx.x * 16LL + grp;
    if (node < n) {
        float dd = g_dis[node];
        float4 bv = *(const float4*)(bias + ch);
        float4 xv = *(const float4*)(xw + node * 64 + ch);
        float w0 = dd * dd;
        float4 acc = make_float4(bv.x + w0 * xv.x, bv.y + w0 * xv.y,
                                 bv.z + w0 * xv.z, bv.w + w0 * xv.w);
        int beg = g_rowptr[node], end = g_rowptr[node + 1];
        int i = beg;
        for (; i + 4 <= end; i += 4) {
            int s0 = g_csr[i], s1 = g_csr[i + 1], s2 = g_csr[i + 2], s3 = g_csr[i + 3];
            float n0 = dd * g_dis[s0], n1 = dd * g_dis[s1];
            float n2 = dd * g_dis[s2], n3 = dd * g_dis[s3];
            float4 v0 = *(const float4*)(xw + (long long)s0 * 64 + ch);
            float4 v1 = *(const float4*)(xw + (long long)s1 * 64 + ch);
            float4 v2 = *(const float4*)(xw + (long long)s2 * 64 + ch);
            float4 v3 = *(const float4*)(xw + (long long)s3 * 64 + ch);
            acc.x += n0 * v0.x + n1 * v1.x + n2 * v2.x + n3 * v3.x;
            acc.y += n0 * v0.y + n1 * v1.y + n2 * v2.y + n3 * v3.y;
            acc.z += n0 * v0.z + n1 * v1.z + n2 * v2.z + n3 * v3.z;
            acc.w += n0 * v0.w + n1 * v1.w + n2 * v2.w + n3 * v3.w;
        }
        for (; i < end; i++) {
            int s = g_csr[i];
            float nn = dd * g_dis[s];
            float4 v = *(const float4*)(xw + (long long)s * 64 + ch);
            acc.x += nn * v.x; acc.y += nn * v.y;
            acc.z += nn * v.z; acc.w += nn * v.w;
        }
        acc.x = fmaxf(acc.x, 0.f); acc.y = fmaxf(acc.y, 0.f);
        acc.z = fmaxf(acc.z, 0.f); acc.w = fmaxf(acc.w, 0.f);
        *(float4*)(out + node * 64 + ch) = acc;
        atomicAdd(&ss[ch + 0], acc.x); atomicAdd(&sq[ch + 0], acc.x * acc.x);
        atomicAdd(&ss[ch + 1], acc.y); atomicAdd(&sq[ch + 1], acc.y * acc.y);
        atomicAdd(&ss[ch + 2], acc.z); atomicAdd(&sq[ch + 2], acc.z * acc.z);
        atomicAdd(&ss[ch + 3], acc.w); atomicAdd(&sq[ch + 3], acc.w * acc.w);
    }
    __syncthreads();
    if (t < HC) { atomicAdd(&gsum[t], ss[t]); atomicAdd(&gsq[t], sq[t]); }
}

// ---------------- BN apply (in place) ----------------------------------------
__global__ void k_bn(float* __restrict__ buf, const float* __restrict__ gsum,
                     const float* __restrict__ gsq, const float* __restrict__ gamma,
                     const float* __restrict__ beta, float invN, long long n64) {
    long long idx = blockIdx.x * (long long)blockDim.x + threadIdx.x;
    if (idx >= n64) return;
    int c = (int)(idx & 63);
    float m   = gsum[c] * invN;
    float var = gsq[c] * invN - m * m;
    float sc  = rsqrtf(var + EPSV) * gamma[c];
    buf[idx] = (buf[idx] - m) * sc + beta[c];
}

// ---------------- BN apply + global mean pool accumulation ------------------
__global__ void k_bnpool(const float* __restrict__ buf, const float* __restrict__ gsum,
                         const float* __restrict__ gsq, const float* __restrict__ gamma,
                         const float* __restrict__ beta, const void* batch,
                         float invN, long long n64) {
    long long idx = blockIdx.x * (long long)blockDim.x + threadIdx.x;
    if (idx >= n64) return;
    long long i = idx >> 6;
    int c = (int)(idx & 63);
    float m   = gsum[c] * invN;
    float var = gsq[c] * invN - m * m;
    float sc  = rsqrtf(var + EPSV) * gamma[c];
    float val = (buf[idx] - m) * sc + beta[c];
    long long b = ld_idx(batch, i);
    atomicAdd(&g_pool[b * 64 + c], val);
    if (c == 0) atomicAdd(&g_cnt[b], 1.0f);
}

// ---------------- fused MLP head: one block per graph ------------------------
__global__ void k_mlp(const float* __restrict__ fw1, const float* __restrict__ fb1,
                      const float* __restrict__ fw2, const float* __restrict__ fb2,
                      const float* __restrict__ fw3, const float* __restrict__ fb3,
                      const float* __restrict__ fw4, const float* __restrict__ fb4,
                      const float* __restrict__ ow,  const float* __restrict__ ob,
                      float* __restrict__ out) {
    __shared__ float p[64], a1[128], a2[64], a3[32], a4[16];
    int g = blockIdx.x, t = threadIdx.x;
    float inv = 1.0f / fmaxf(g_cnt[g], 1.0f);
    if (t < 64) p[t] = g_pool[g * 64 + t] * inv;
    __syncthreads();
    if (t < 128) {
        float a = fb1[t];
#pragma unroll 8
        for (int k = 0; k < 64; k++) a += p[k] * fw1[k * 128 + t];
        a1[t] = fmaxf(a, 0.f);
    }
    __syncthreads();
    if (t < 64) {
        float a = fb2[t];
#pragma unroll 8
        for (int k = 0; k < 128; k++) a += a1[k] * fw2[k * 64 + t];
        a2[t] = fmaxf(a, 0.f);
    }
    __syncthreads();
    if (t < 32) {
        float a = fb3[t];
#pragma unroll 8
        for (int k = 0; k < 64; k++) a += a2[k] * fw3[k * 32 + t];
        a3[t] = fmaxf(a, 0.f);
    }
    __syncthreads();
    if (t < 16) {
        float a = fb4[t];
#pragma unroll
        for (int k = 0; k < 32; k++) a += a3[k] * fw4[k * 16 + t];
        a4[t] = fmaxf(a, 0.f);
    }
    __syncthreads();
    if (t < 2) {
        float a = ob[t];
#pragma unroll
        for (int k = 0; k < 16; k++) a += a4[k] * ow[k * 2 + t];
        out[g * 2 + t] = a;
    }
}

// ---------------- launcher ------------------------------------------------------
extern "C" void kernel_launch(void* const* d_in, const int* in_sizes, int n_in,
                              void* d_out, int out_size) {
    const float* x   = (const float*)d_in[0];
    const void*  ei  = d_in[1];
    const void*  bat = d_in[2];
    const float* w1  = (const float*)d_in[3];
    const float* b1  = (const float*)d_in[4];
    const float* w2  = (const float*)d_in[5];
    const float* b2  = (const float*)d_in[6];
    const float* g1  = (const float*)d_in[7];
    const float* be1 = (const float*)d_in[8];
    const float* g2  = (const float*)d_in[9];
    const float* be2 = (const float*)d_in[10];
    const float* fw1 = (const float*)d_in[11];
    const float* fb1 = (const float*)d_in[12];
    const float* fw2 = (const float*)d_in[13];
    const float* fb2 = (const float*)d_in[14];
    const float* fw3 = (const float*)d_in[15];
    const float* fb3 = (const float*)d_in[16];
    const float* fw4 = (const float*)d_in[17];
    const float* fb4 = (const float*)d_in[18];
    const float* ow  = (const float*)d_in[19];
    const float* ob  = (const float*)d_in[20];
    float* out = (float*)d_out;

    const long long N = in_sizes[0] / 256;   // C = 256
    const long long E = in_sizes[1] / 2;
    const int       G = out_size / 2;
    const long long n64 = N * 64;
    const float invN = 1.0f / (float)N;

    float *bufA, *bufB, *sum1, *sq1, *sum2, *sq2;
    cudaGetSymbolAddress((void**)&bufA, g_bufA);
    cudaGetSymbolAddress((void**)&bufB, g_bufB);
    cudaGetSymbolAddress((void**)&sum1, g_sum1);
    cudaGetSymbolAddress((void**)&sq1,  g_sq1);
    cudaGetSymbolAddress((void**)&sum2, g_sum2);
    cudaGetSymbolAddress((void**)&sq2,  g_sq2);

    const int TB = 256;
    const int gN    = (int)((N + TB - 1) / TB);
    const int gE    = (int)((E + TB - 1) / TB);
    const int gN64  = (int)((n64 + TB - 1) / TB);
    const int gGemm = (int)((N + 63) / 64);
    const int gGath = (int)((N + 15) / 16);
    const int nb    = (int)((N + 255) / 256);

    // ---- fork: GEMM1 (independent of CSR/index state) on side stream ----
    cudaEventRecord(hx_fork, 0);
    cudaStreamWaitEvent(hx_s2, hx_fork, 0);
    k_gemm<256><<<gGemm, 128, 0, hx_s2>>>(x, w1, bufA, N);
    cudaEventRecord(hx_join, hx_s2);

    // ---- CSR build chain on the main stream ----
    k_detect<<<1, 1>>>(ei, N);
    k_zero<<<gN, TB>>>(N);
    k_hist<<<gE, TB>>>(ei, E);
    k_scan1<<<nb, 256>>>(N);
    k_scan2<<<1, 512>>>(nb);
    k_scan3<<<gN, TB>>>(N, (int)E);
    k_scatter<<<gE, TB>>>(ei, E);

    // ---- join: gather1 needs both CSR and GEMM1 output ----
    cudaStreamWaitEvent(0, hx_join, 0);

    // ---- GCN layer 1 tail ----
    k_gather<<<gGath, 256>>>(bufA, b1, bufB, N, sum1, sq1);
    k_bn<<<gN64, TB>>>(bufB, sum1, sq1, g1, be1, invN, n64);

    // ---- GCN layer 2 ----
    k_gemm<64><<<gGemm, 128>>>(bufB, w2, bufA, N);
    k_gather<<<gGath, 256>>>(bufA, b2, bufB, N, sum2, sq2);
    k_bnpool<<<gN64, TB>>>(bufB, sum2, sq2, g2, be2, bat, invN, n64);

    // ---- MLP head ----
    k_mlp<<<G, 128>>>(fw1, fb1, fw2, fb2, fw3, fb3, fw4, fb4, ow, ob, out);
}

// round 10
// speedup vs baseline: 1.5771x; 1.0993x over previous
#include <cuda_runtime.h>
#include <cuda_fp16.h>

typedef unsigned long long ull;

// ---------------- problem constants (shapes fixed by the dataset) -----------
#define MAXN 100000
#define MAXE 3342336
#define HC   64
#define MAXG 512
#define EPSV 1e-5f

// ---------------- device scratch (static; no allocation) --------------------
__device__ __half g_bufH[MAXN * HC];     // projected features (xW), fp16
__device__ float  g_bufB[MAXN * HC];     // aggregated features (h), fp32
__device__ float  g_dis[MAXN];           // rsqrt(deg)
__device__ int    g_deg[MAXN];           // in-degree (w/o self loop)
__device__ int    g_rowptr[MAXN + 1];
__device__ int    g_cursor[MAXN];
__device__ int    g_csr[MAXE];           // src ids grouped by dst
__device__ int    g_bsum[512];
__device__ int    g_boff[512];
__device__ float  g_sum1[HC], g_sq1[HC], g_sum2[HC], g_sq2[HC];
__device__ float  g_pool[MAXG * HC];
__device__ float  g_cnt[MAXG];
__device__ int    g_is64;

// ---------------- host-side stream/event objects (created pre-main) ---------
static cudaStream_t hx_s2;
static cudaEvent_t  hx_fork, hx_join;
namespace {
struct HXInit {
    HXInit() {
        cudaStreamCreateWithFlags(&hx_s2, cudaStreamNonBlocking);
        cudaEventCreateWithFlags(&hx_fork, cudaEventDisableTiming);
        cudaEventCreateWithFlags(&hx_join, cudaEventDisableTiming);
    }
};
static HXInit hx_init;
}

// ---------------- dtype-agnostic index load ---------------------------------
__device__ __forceinline__ long long ld_idx(const void* p, long long i) {
    if (g_is64) return ((const long long*)p)[i];
    return (long long)((const int*)p)[i];
}

__global__ void k_detect(const void* ei, long long n_nodes) {
    const long long* p = (const long long*)ei;
    int ok = 1;
    for (int i = 0; i < 64; i++) {
        long long v = p[i];
        if (v < 0 || v >= n_nodes) { ok = 0; break; }
    }
    g_is64 = ok;
}

// ---------------- packed f32x2 helpers (Blackwell) --------------------------
__device__ __forceinline__ ull dupf(float a) {
    ull r; unsigned int u = __float_as_uint(a);
    asm("mov.b64 %0, {%1, %1};" : "=l"(r) : "r"(u));
    return r;
}
__device__ __forceinline__ void ffma2(ull& d, ull a, ull b) {
    asm("fma.rn.f32x2 %0, %1, %2, %0;" : "+l"(d) : "l"(a), "l"(b));
}
__device__ __forceinline__ float2 unpk(ull v) {
    unsigned int lo, hi;
    asm("mov.b64 {%0, %1}, %2;" : "=r"(lo), "=r"(hi) : "l"(v));
    return make_float2(__uint_as_float(lo), __uint_as_float(hi));
}

// ---------------- init: zero deg/pool/cnt/bn sums ----------------------------
__global__ void k_zero(long long n) {
    long long i = blockIdx.x * (long long)blockDim.x + threadIdx.x;
    if (i < n)          g_deg[i] = 0;
    if (i < MAXG * HC)  g_pool[i] = 0.0f;
    if (i < MAXG)       g_cnt[i] = 0.0f;
    if (i < HC) { g_sum1[i] = 0.f; g_sq1[i] = 0.f; g_sum2[i] = 0.f; g_sq2[i] = 0.f; }
}

__global__ void k_hist(const void* ei, long long E) {
    long long e = blockIdx.x * (long long)blockDim.x + threadIdx.x;
    if (e >= E) return;
    atomicAdd(&g_deg[ld_idx(ei, E + e)], 1);
}

// ---------------- exclusive scan over g_deg ------------------------------------
__global__ void k_scan1(long long n) {
    __shared__ int wsum[8];
    int t = threadIdx.x;
    long long i = blockIdx.x * 256LL + t;
    int v = (i < n) ? g_deg[i] : 0;
    int x = v;
#pragma unroll
    for (int o = 1; o < 32; o <<= 1) {
        int y = __shfl_up_sync(~0u, x, o);
        if ((t & 31) >= o) x += y;
    }
    if ((t & 31) == 31) wsum[t >> 5] = x;
    __syncthreads();
    if (t < 8) {
        int y = wsum[t];
#pragma unroll
        for (int o = 1; o < 8; o <<= 1) {
            int z = __shfl_up_sync(0xff, y, o);
            if (t >= o) y += z;
        }
        wsum[t] = y;
    }
    __syncthreads();
    int base = (t >= 32) ? wsum[(t >> 5) - 1] : 0;
    int incl = x + base;
    if (i < n) g_rowptr[i] = incl - v;
    if (t == 255) g_bsum[blockIdx.x] = incl;
}

__global__ void k_scan2(int nb) {
    __shared__ int wsum[16];
    int t = threadIdx.x;
    int v = (t < nb) ? g_bsum[t] : 0;
    int x = v;
#pragma unroll
    for (int o = 1; o < 32; o <<= 1) {
        int y = __shfl_up_sync(~0u, x, o);
        if ((t & 31) >= o) x += y;
    }
    if ((t & 31) == 31) wsum[t >> 5] = x;
    __syncthreads();
    if (t < 16) {
        int y = wsum[t];
#pragma unroll
        for (int o = 1; o < 16; o <<= 1) {
            int z = __shfl_up_sync(0xffff, y, o);
            if (t >= o) y += z;
        }
        wsum[t] = y;
    }
    __syncthreads();
    int base = (t >= 32) ? wsum[(t >> 5) - 1] : 0;
    g_boff[t] = x + base - v;
}

__global__ void k_scan3(long long n, int E) {
    long long i = blockIdx.x * (long long)blockDim.x + threadIdx.x;
    if (i < n) {
        int rp = g_rowptr[i] + g_boff[i >> 8];
        g_rowptr[i] = rp;
        g_cursor[i] = rp;
        g_dis[i] = rsqrtf((float)(g_deg[i] + 1));
    }
    if (i == 0) g_rowptr[n] = E;
}

__global__ void k_scatter(const void* ei, long long E) {
    long long e = blockIdx.x * (long long)blockDim.x + threadIdx.x;
    if (e >= E) return;
    long long s = ld_idx(ei, e);
    long long d = ld_idx(ei, E + e);
    int pos = atomicAdd(&g_cursor[d], 1);
    g_csr[pos] = (int)s;
}

// ---------------- GEMM: C[N,64] = A[N,K] @ W[K,64], fp16 output --------------
// 128 threads, block tile 64x64, thread tile 4x8 (8 rows x 4 cols),
// packed f32x2 accumulators. Pad 68 keeps every row 16B-aligned (68*4=272).
template <int K>
__global__ void k_gemm(const float* __restrict__ A, const float* __restrict__ W,
                       __half* __restrict__ C, long long n) {
    __shared__ __align__(16) float xsT[32][68];   // [k][row]; 272B row stride
    __shared__ __align__(16) float ws[32][64];    // [k][col]
    const int tid = threadIdx.x;
    const int tx = tid & 15;        // col group: 4 cols
    const int ty = tid >> 4;        // row group: 8 rows
    const long long row0 = (long long)blockIdx.x * 64;
    ull acc[8][2] = {};

    const int lrow = tid >> 1;              // 0..63  row this thread loads
    const int lko  = (tid & 1) * 16;        // k-offset 0 or 16
    const long long grow = row0 + lrow;
    const bool rok = grow < n;

    for (int k0 = 0; k0 < K; k0 += 32) {
        float4 xv[4];
        if (rok) {
            const float* src = A + grow * (long long)K + k0 + lko;
#pragma unroll
            for (int q = 0; q < 4; q++) xv[q] = *(const float4*)(src + q * 4);
        } else {
#pragma unroll
            for (int q = 0; q < 4; q++) xv[q] = make_float4(0.f, 0.f, 0.f, 0.f);
        }
        float4 wv[4];
#pragma unroll
        for (int j = 0; j < 4; j++) {
            int fi = tid + j * 128;
            int kk = fi >> 4;
            int cc = (fi & 15) * 4;
            wv[j] = *(const float4*)(W + (long long)(k0 + kk) * 64 + cc);
        }
        __syncthreads();
#pragma unroll
        for (int q = 0; q < 4; q++) {
            xsT[lko + q * 4 + 0][lrow] = xv[q].x;
            xsT[lko + q * 4 + 1][lrow] = xv[q].y;
            xsT[lko + q * 4 + 2][lrow] = xv[q].z;
            xsT[lko + q * 4 + 3][lrow] = xv[q].w;
        }
#pragma unroll
        for (int j = 0; j < 4; j++) {
            int fi = tid + j * 128;
            int kk = fi >> 4;
            int cc = (fi & 15) * 4;
            *(float4*)&ws[kk][cc] = wv[j];
        }
        __syncthreads();
#pragma unroll
        for (int kk = 0; kk < 32; kk++) {
            float4 a0 = *(const float4*)&xsT[kk][ty * 8];
            float4 a1 = *(const float4*)&xsT[kk][ty * 8 + 4];
            const ull* bp = (const ull*)&ws[kk][tx * 4];
            ull b01 = bp[0], b23 = bp[1];
            ull a;
            a = dupf(a0.x); ffma2(acc[0][0], a, b01); ffma2(acc[0][1], a, b23);
            a = dupf(a0.y); ffma2(acc[1][0], a, b01); ffma2(acc[1][1], a, b23);
            a = dupf(a0.z); ffma2(acc[2][0], a, b01); ffma2(acc[2][1], a, b23);
            a = dupf(a0.w); ffma2(acc[3][0], a, b01); ffma2(acc[3][1], a, b23);
            a = dupf(a1.x); ffma2(acc[4][0], a, b01); ffma2(acc[4][1], a, b23);
            a = dupf(a1.y); ffma2(acc[5][0], a, b01); ffma2(acc[5][1], a, b23);
            a = dupf(a1.z); ffma2(acc[6][0], a, b01); ffma2(acc[6][1], a, b23);
            a = dupf(a1.w); ffma2(acc[7][0], a, b01); ffma2(acc[7][1], a, b23);
        }
        __syncthreads();
    }
#pragma unroll
    for (int i = 0; i < 8; i++) {
        long long row = row0 + ty * 8 + i;
        if (row < n) {
            float2 c0 = unpk(acc[i][0]), c1 = unpk(acc[i][1]);
            __half2 h0 = __floats2half2_rn(c0.x, c0.y);
            __half2 h1 = __floats2half2_rn(c1.x, c1.y);
            uint2 u;
            u.x = *(unsigned int*)&h0;
            u.y = *(unsigned int*)&h1;
            *(uint2*)(C + row * 64 + tx * 4) = u;
        }
    }
}

// ---------------- fused CSR gather (fp16 src): bias + agg + relu + stats ----
__global__ void k_gather(const __half* __restrict__ xwh, const float* __restrict__ bias,
                         float* __restrict__ out, long long n,
                         float* __restrict__ gsum, float* __restrict__ gsq) {
    __shared__ float ss[HC], sq[HC];
    int t = threadIdx.x;
    if (t < HC) { ss[t] = 0.f; sq[t] = 0.f; }
    __syncthreads();
    int grp = t >> 4;
    int ch  = (t & 15) * 4;
    long long node = blockIdx.x * 16LL + grp;
    if (node < n) {
        float dd = g_dis[node];
        float4 bv = *(const float4*)(bias + ch);
        uint2 su = *(const uint2*)(xwh + node * 64 + ch);
        float2 s0f = __half22float2(*(__half2*)&su.x);
        float2 s1f = __half22float2(*(__half2*)&su.y);
        float w0 = dd * dd;
        float4 acc = make_float4(bv.x + w0 * s0f.x, bv.y + w0 * s0f.y,
                                 bv.z + w0 * s1f.x, bv.w + w0 * s1f.y);
        int beg = g_rowptr[node], end = g_rowptr[node + 1];
        int i = beg;
        for (; i + 4 <= end; i += 4) {
            int e0 = g_csr[i], e1 = g_csr[i + 1], e2 = g_csr[i + 2], e3 = g_csr[i + 3];
            float n0 = dd * g_dis[e0], n1 = dd * g_dis[e1];
            float n2 = dd * g_dis[e2], n3 = dd * g_dis[e3];
            uint2 u0 = *(const uint2*)(xwh + (long long)e0 * 64 + ch);
            uint2 u1 = *(const uint2*)(xwh + (long long)e1 * 64 + ch);
            uint2 u2 = *(const uint2*)(xwh + (long long)e2 * 64 + ch);
            uint2 u3 = *(const uint2*)(xwh + (long long)e3 * 64 + ch);
            float2 a0 = __half22float2(*(__half2*)&u0.x), b0 = __half22float2(*(__half2*)&u0.y);
            float2 a1 = __half22float2(*(__half2*)&u1.x), b1 = __half22float2(*(__half2*)&u1.y);
            float2 a2 = __half22float2(*(__half2*)&u2.x), b2 = __half22float2(*(__half2*)&u2.y);
            float2 a3 = __half22float2(*(__half2*)&u3.x), b3 = __half22float2(*(__half2*)&u3.y);
            acc.x += n0 * a0.x + n1 * a1.x + n2 * a2.x + n3 * a3.x;
            acc.y += n0 * a0.y + n1 * a1.y + n2 * a2.y + n3 * a3.y;
            acc.z += n0 * b0.x + n1 * b1.x + n2 * b2.x + n3 * b3.x;
            acc.w += n0 * b0.y + n1 * b1.y + n2 * b2.y + n3 * b3.y;
        }
        for (; i < end; i++) {
            int s = g_csr[i];
            float nn = dd * g_dis[s];
            uint2 u = *(const uint2*)(xwh + (long long)s * 64 + ch);
            float2 a = __half22float2(*(__half2*)&u.x), b = __half22float2(*(__half2*)&u.y);
            acc.x += nn * a.x; acc.y += nn * a.y;
            acc.z += nn * b.x; acc.w += nn * b.y;
        }
        acc.x = fmaxf(acc.x, 0.f); acc.y = fmaxf(acc.y, 0.f);
        acc.z = fmaxf(acc.z, 0.f); acc.w = fmaxf(acc.w, 0.f);
        *(float4*)(out + node * 64 + ch) = acc;
        atomicAdd(&ss[ch + 0], acc.x); atomicAdd(&sq[ch + 0], acc.x * acc.x);
        atomicAdd(&ss[ch + 1], acc.y); atomicAdd(&sq[ch + 1], acc.y * acc.y);
        atomicAdd(&ss[ch + 2], acc.z); atomicAdd(&sq[ch + 2], acc.z * acc.z);
        atomicAdd(&ss[ch + 3], acc.w); atomicAdd(&sq[ch + 3], acc.w * acc.w);
    }
    __syncthreads();
    if (t < HC) { atomicAdd(&gsum[t], ss[t]); atomicAdd(&gsq[t], sq[t]); }
}

// ---------------- BN apply (in place) ----------------------------------------
__global__ void k_bn(float* __restrict__ buf, const float* __restrict__ gsum,
                     const float* __restrict__ gsq, const float* __restrict__ gamma,
                     const float* __restrict__ beta, float invN, long long n64) {
    long long idx = blockIdx.x * (long long)blockDim.x + threadIdx.x;
    if (idx >= n64) return;
    int c = (int)(idx & 63);
    float m   = gsum[c] * invN;
    float var = gsq[c] * invN - m * m;
    float sc  = rsqrtf(var + EPSV) * gamma[c];
    buf[idx] = (buf[idx] - m) * sc + beta[c];
}

// ---------------- BN apply + global mean pool accumulation ------------------
__global__ void k_bnpool(const float* __restrict__ buf, const float* __restrict__ gsum,
                         const float* __restrict__ gsq, const float* __restrict__ gamma,
                         const float* __restrict__ beta, const void* batch,
                         float invN, long long n64) {
    long long idx = blockIdx.x * (long long)blockDim.x + threadIdx.x;
    if (idx >= n64) return;
    long long i = idx >> 6;
    int c = (int)(idx & 63);
    float m   = gsum[c] * invN;
    float var = gsq[c] * invN - m * m;
    float sc  = rsqrtf(var + EPSV) * gamma[c];
    float val = (buf[idx] - m) * sc + beta[c];
    long long b = ld_idx(batch, i);
    atomicAdd(&g_pool[b * 64 + c], val);
    if (c == 0) atomicAdd(&g_cnt[b], 1.0f);
}

// ---------------- fused MLP head: one block per graph ------------------------
__global__ void k_mlp(const float* __restrict__ fw1, const float* __restrict__ fb1,
                      const float* __restrict__ fw2, const float* __restrict__ fb2,
                      const float* __restrict__ fw3, const float* __restrict__ fb3,
                      const float* __restrict__ fw4, const float* __restrict__ fb4,
                      const float* __restrict__ ow,  const float* __restrict__ ob,
                      float* __restrict__ out) {
    __shared__ float p[64], a1[128], a2[64], a3[32], a4[16];
    int g = blockIdx.x, t = threadIdx.x;
    float inv = 1.0f / fmaxf(g_cnt[g], 1.0f);
    if (t < 64) p[t] = g_pool[g * 64 + t] * inv;
    __syncthreads();
    if (t < 128) {
        float a = fb1[t];
#pragma unroll 8
        for (int k = 0; k < 64; k++) a += p[k] * fw1[k * 128 + t];
        a1[t] = fmaxf(a, 0.f);
    }
    __syncthreads();
    if (t < 64) {
        float a = fb2[t];
#pragma unroll 8
        for (int k = 0; k < 128; k++) a += a1[k] * fw2[k * 64 + t];
        a2[t] = fmaxf(a, 0.f);
    }
    __syncthreads();
    if (t < 32) {
        float a = fb3[t];
#pragma unroll 8
        for (int k = 0; k < 64; k++) a += a2[k] * fw3[k * 32 + t];
        a3[t] = fmaxf(a, 0.f);
    }
    __syncthreads();
    if (t < 16) {
        float a = fb4[t];
#pragma unroll
        for (int k = 0; k < 32; k++) a += a3[k] * fw4[k * 16 + t];
        a4[t] = fmaxf(a, 0.f);
    }
    __syncthreads();
    if (t < 2) {
        float a = ob[t];
#pragma unroll
        for (int k = 0; k < 16; k++) a += a4[k] * ow[k * 2 + t];
        out[g * 2 + t] = a;
    }
}

// ---------------- launcher ------------------------------------------------------
extern "C" void kernel_launch(void* const* d_in, const int* in_sizes, int n_in,
                              void* d_out, int out_size) {
    const float* x   = (const float*)d_in[0];
    const void*  ei  = d_in[1];
    const void*  bat = d_in[2];
    const float* w1  = (const float*)d_in[3];
    const float* b1  = (const float*)d_in[4];
    const float* w2  = (const float*)d_in[5];
    const float* b2  = (const float*)d_in[6];
    const float* g1  = (const float*)d_in[7];
    const float* be1 = (const float*)d_in[8];
    const float* g2  = (const float*)d_in[9];
    const float* be2 = (const float*)d_in[10];
    const float* fw1 = (const float*)d_in[11];
    const float* fb1 = (const float*)d_in[12];
    const float* fw2 = (const float*)d_in[13];
    const float* fb2 = (const float*)d_in[14];
    const float* fw3 = (const float*)d_in[15];
    const float* fb3 = (const float*)d_in[16];
    const float* fw4 = (const float*)d_in[17];
    const float* fb4 = (const float*)d_in[18];
    const float* ow  = (const float*)d_in[19];
    const float* ob  = (const float*)d_in[20];
    float* out = (float*)d_out;

    const long long N = in_sizes[0] / 256;   // C = 256
    const long long E = in_sizes[1] / 2;
    const int       G = out_size / 2;
    const long long n64 = N * 64;
    const float invN = 1.0f / (float)N;

    __half* bufH;
    float *bufB, *sum1, *sq1, *sum2, *sq2;
    cudaGetSymbolAddress((void**)&bufH, g_bufH);
    cudaGetSymbolAddress((void**)&bufB, g_bufB);
    cudaGetSymbolAddress((void**)&sum1, g_sum1);
    cudaGetSymbolAddress((void**)&sq1,  g_sq1);
    cudaGetSymbolAddress((void**)&sum2, g_sum2);
    cudaGetSymbolAddress((void**)&sq2,  g_sq2);

    const int TB = 256;
    const int gN    = (int)((N + TB - 1) / TB);
    const int gE    = (int)((E + TB - 1) / TB);
    const int gN64  = (int)((n64 + TB - 1) / TB);
    const int gGemm = (int)((N + 63) / 64);
    const int gGath = (int)((N + 15) / 16);
    const int nb    = (int)((N + 255) / 256);

    // ---- fork: GEMM1 (independent of CSR/index state) on side stream ----
    cudaEventRecord(hx_fork, 0);
    cudaStreamWaitEvent(hx_s2, hx_fork, 0);
    k_gemm<256><<<gGemm, 128, 0, hx_s2>>>(x, w1, bufH, N);
    cudaEventRecord(hx_join, hx_s2);

    // ---- CSR build chain on the main stream ----
    k_detect<<<1, 1>>>(ei, N);
    k_zero<<<gN, TB>>>(N);
    k_hist<<<gE, TB>>>(ei, E);
    k_scan1<<<nb, 256>>>(N);
    k_scan2<<<1, 512>>>(nb);
    k_scan3<<<gN, TB>>>(N, (int)E);
    k_scatter<<<gE, TB>>>(ei, E);

    // ---- join: gather1 needs both CSR and GEMM1 output ----
    cudaStreamWaitEvent(0, hx_join, 0);

    // ---- GCN layer 1 tail ----
    k_gather<<<gGath, 256>>>(bufH, b1, bufB, N, sum1, sq1);
    k_bn<<<gN64, TB>>>(bufB, sum1, sq1, g1, be1, invN, n64);

    // ---- GCN layer 2 ----
    k_gemm<64><<<gGemm, 128>>>(bufB, w2, bufH, N);
    k_gather<<<gGath, 256>>>(bufH, b2, bufB, N, sum2, sq2);
    k_bnpool<<<gN64, TB>>>(bufB, sum2, sq2, g2, be2, bat, invN, n64);

    // ---- MLP head ----
    k_mlp<<<G, 128>>>(fw1, fb1, fw2, fb2, fw3, fb3, fw4, fb4, ow, ob, out);
}